// round 6
// baseline (speedup 1.0000x reference)
#include <cuda_runtime.h>
#include <math.h>
#include <stdint.h>

#define B_    8
#define HW_   4096
#define K_    256
#define HID_  1024
#define AUX_  512
#define QK_   512
#define NH_   8
#define HD_   128
#define SCALE_ 0.08838834764831845f   // 1/sqrt(128)

__device__ float g_scratch[108003328];

// ---------------- helpers -----------------------------------------------------
__device__ __forceinline__ uint32_t f2tf32(float f) {
    uint32_t u;
    asm("cvt.rna.tf32.f32 %0, %1;" : "=r"(u) : "f"(f));
    return u;
}
__device__ __forceinline__ void mma8(float* c, const uint32_t* a, const uint32_t* b) {
    asm volatile(
        "mma.sync.aligned.m16n8k8.row.col.f32.tf32.tf32.f32 "
        "{%0,%1,%2,%3}, {%4,%5,%6,%7}, {%8,%9}, {%0,%1,%2,%3};"
        : "+f"(c[0]), "+f"(c[1]), "+f"(c[2]), "+f"(c[3])
        : "r"(a[0]), "r"(a[1]), "r"(a[2]), "r"(a[3]), "r"(b[0]), "r"(b[1]));
}
__device__ __forceinline__ void cp16(void* s, const void* g) {
    uint32_t sa = (uint32_t)__cvta_generic_to_shared(s);
    asm volatile("cp.async.cg.shared.global [%0], [%1], 16;" :: "r"(sa), "l"(g));
}

// ======== big-tile TRANSB GEMM: C[M,N] = alpha*A[M,K]*B[N,K]^T + bias =========
// CTA tile 128x256, BK=16, 3-stage cp.async ring, 8 warps at 64x64 each.
// M mult of 128, N mult of 256, K mult of 16 (and >= 48 handled: nchunk>=3 via
// guarded prologue). Batched over blockIdx.z.
#define BG_ASTG (128 * 20)
#define BG_BSTG (256 * 20)
#define BG_SMEM (3 * (BG_ASTG + BG_BSTG) * 4)

__global__ __launch_bounds__(256, 1) void mma_gemm_big(
    const float* __restrict__ A, const float* __restrict__ Bm,
    const float* __restrict__ bias, float* __restrict__ C,
    int Kd, int lda, int ldb, int ldc_,
    long long sAb, long long sAh, long long sBb, long long sBh,
    long long sCb, long long sCh, int nh, float alpha)
{
    extern __shared__ float sm[];
    float* AsB = sm;
    float* BsB = sm + 3 * BG_ASTG;

    const int z  = blockIdx.z;
    const int bb = z / nh, hh = z - bb * nh;
    A  += bb * sAb + hh * sAh;
    Bm += bb * sBb + hh * sBh;
    C  += bb * sCb + hh * sCh;

    const int m0   = blockIdx.y * 128;
    const int n0   = blockIdx.x * 256;
    const int t    = threadIdx.x;
    const int lane = t & 31;
    const int warp = t >> 5;
    const int wm   = (warp >> 2) * 64;   // 2 warps in M
    const int wn   = (warp & 3) * 64;    // 4 warps in N
    const int gid  = lane >> 2;
    const int tig  = lane & 3;

    float acc[4][8][4];
#pragma unroll
    for (int i = 0; i < 4; i++)
#pragma unroll
        for (int j = 0; j < 8; j++)
#pragma unroll
            for (int r = 0; r < 4; r++) acc[i][j][r] = 0.f;

    auto loadA = [&](int s, int k0) {
        float* As = AsB + s * BG_ASTG;
#pragma unroll
        for (int i = 0; i < 2; i++) {
            int c = t + i * 256;
            int row = c >> 2, off = (c & 3) * 4;
            cp16(&As[row * 20 + off], A + (size_t)(m0 + row) * lda + k0 + off);
        }
    };
    auto loadB = [&](int s, int k0) {
        float* Bs = BsB + s * BG_BSTG;
#pragma unroll
        for (int i = 0; i < 4; i++) {
            int c = t + i * 256;
            int row = c >> 2, off = (c & 3) * 4;
            cp16(&Bs[row * 20 + off], Bm + (size_t)(n0 + row) * ldb + k0 + off);
        }
    };

    const int nchunk = Kd >> 4;
    loadA(0, 0); loadB(0, 0);
    asm volatile("cp.async.commit_group;");
    if (nchunk > 1) { loadA(1, 16); loadB(1, 16); }
    asm volatile("cp.async.commit_group;");
    if (nchunk > 2) { loadA(2, 32); loadB(2, 32); }
    asm volatile("cp.async.commit_group;");

    for (int ck = 0; ck < nchunk; ck++) {
        asm volatile("cp.async.wait_group 2;");
        __syncthreads();
        if (ck + 3 < nchunk) {
            const int s2 = (ck + 3) % 3;   // == ck%3 slot freed after this sync? no:
            // slot (ck+3)%3 == ck%3 is IN USE this iteration; prefetch goes to the
            // slot that finished last iteration: (ck-1)%3 == (ck+2)%3. Use ck+3 only
            // after compute. So prefetch below compute instead.
        }

        const int s = ck % 3;
        const float* As = AsB + s * BG_ASTG;
        const float* Bs = BsB + s * BG_BSTG;
#pragma unroll
        for (int k8 = 0; k8 < 16; k8 += 8) {
            uint32_t af[4][4], bf[8][2];
            const int kk = k8 + tig;
#pragma unroll
            for (int mt = 0; mt < 4; mt++) {
                const int r = wm + mt * 16 + gid;
                af[mt][0] = f2tf32(As[r * 20 + kk]);
                af[mt][1] = f2tf32(As[(r + 8) * 20 + kk]);
                af[mt][2] = f2tf32(As[r * 20 + kk + 4]);
                af[mt][3] = f2tf32(As[(r + 8) * 20 + kk + 4]);
            }
#pragma unroll
            for (int nt = 0; nt < 8; nt++) {
                const int col = wn + nt * 8 + gid;
                bf[nt][0] = f2tf32(Bs[col * 20 + kk]);
                bf[nt][1] = f2tf32(Bs[col * 20 + kk + 4]);
            }
#pragma unroll
            for (int mt = 0; mt < 4; mt++)
#pragma unroll
                for (int nt = 0; nt < 8; nt++)
                    mma8(acc[mt][nt], af[mt], bf[nt]);
        }
        __syncthreads();
        if (ck + 3 < nchunk) {
            const int s2 = ck % 3;          // this stage is now consumed
            loadA(s2, (ck + 3) << 4);
            loadB(s2, (ck + 3) << 4);
        }
        asm volatile("cp.async.commit_group;");
    }

#pragma unroll
    for (int mt = 0; mt < 4; mt++) {
        const int row = m0 + wm + mt * 16 + gid;
#pragma unroll
        for (int nt = 0; nt < 8; nt++) {
            const int col = n0 + wn + nt * 8 + tig * 2;
            float b0v = 0.f, b1v = 0.f;
            if (bias) { b0v = bias[col]; b1v = bias[col + 1]; }
#pragma unroll
            for (int half = 0; half < 2; half++) {
                float2 v;
                v.x = acc[mt][nt][half * 2 + 0] * alpha + b0v;
                v.y = acc[mt][nt][half * 2 + 1] * alpha + b1v;
                *reinterpret_cast<float2*>(C + (size_t)(row + half * 8) * ldc_ + col) = v;
            }
        }
    }
}

// ---------------- NN GEMM (attn @ V), proven 128x128 config -------------------
__global__ __launch_bounds__(256) void mma_gemm_nn(
    const float* __restrict__ A, const float* __restrict__ Bm,
    const float* __restrict__ bias, float* __restrict__ C,
    int M, int N, int Kd, int lda, int ldb, int ldc_,
    long long sAb, long long sAh, long long sBb, long long sBh,
    long long sCb, long long sCh, int nh, float alpha)
{
    constexpr int LDA_S = 20;
    constexpr int ASTG  = 128 * LDA_S;
    constexpr int BSTG  = 16 * 136;
    extern __shared__ float sm[];
    float* AsB = sm;
    float* BsB = sm + 3 * ASTG;

    const int z  = blockIdx.z;
    const int bb = z / nh, hh = z - bb * nh;
    A  += bb * sAb + hh * sAh;
    Bm += bb * sBb + hh * sBh;
    C  += bb * sCb + hh * sCh;

    const int m0   = blockIdx.y * 128;
    const int n0   = blockIdx.x * 128;
    const int t    = threadIdx.x;
    const int lane = t & 31;
    const int warp = t >> 5;
    const int wm   = (warp >> 2) * 64;
    const int wn   = (warp & 3) * 32;
    const int gid  = lane >> 2;
    const int tig  = lane & 3;

    float acc[4][4][4];
#pragma unroll
    for (int i = 0; i < 4; i++)
#pragma unroll
        for (int j = 0; j < 4; j++)
#pragma unroll
            for (int r = 0; r < 4; r++) acc[i][j][r] = 0.f;

    auto loadA = [&](int s, int k0) {
        float* As = AsB + s * ASTG;
#pragma unroll
        for (int i = 0; i < 2; i++) {
            int c = t + i * 256;
            int row = c >> 2, off = (c & 3) * 4;
            cp16(&As[row * LDA_S + off], A + (size_t)(m0 + row) * lda + k0 + off);
        }
    };
    auto loadB = [&](int s, int k0) {
        float* Bs = BsB + s * BSTG;
#pragma unroll
        for (int i = 0; i < 2; i++) {
            int c = t + i * 256;
            int row = c >> 5, off = (c & 31) * 4;
            cp16(&Bs[row * 136 + off], Bm + (size_t)(k0 + row) * ldb + n0 + off);
        }
    };

    const int nchunk = Kd >> 4;
    loadA(0, 0); loadB(0, 0);
    asm volatile("cp.async.commit_group;");
    if (nchunk > 1) { loadA(1, 16); loadB(1, 16); }
    asm volatile("cp.async.commit_group;");

    for (int ck = 0; ck < nchunk; ck++) {
        asm volatile("cp.async.wait_group 1;");
        __syncthreads();
        if (ck + 2 < nchunk) {
            const int s2 = (ck + 2) % 3;
            loadA(s2, (ck + 2) << 4);
            loadB(s2, (ck + 2) << 4);
        }
        asm volatile("cp.async.commit_group;");

        const int s = ck % 3;
        const float* As = AsB + s * ASTG;
        const float* Bs = BsB + s * BSTG;
#pragma unroll
        for (int k8 = 0; k8 < 16; k8 += 8) {
            uint32_t af[4][4], bf[4][2];
            const int kk = k8 + tig;
#pragma unroll
            for (int mt = 0; mt < 4; mt++) {
                const int r = wm + mt * 16 + gid;
                af[mt][0] = f2tf32(As[r * LDA_S + kk]);
                af[mt][1] = f2tf32(As[(r + 8) * LDA_S + kk]);
                af[mt][2] = f2tf32(As[r * LDA_S + kk + 4]);
                af[mt][3] = f2tf32(As[(r + 8) * LDA_S + kk + 4]);
            }
#pragma unroll
            for (int nt = 0; nt < 4; nt++) {
                const int col = wn + nt * 8 + gid;
                bf[nt][0] = f2tf32(Bs[kk * 136 + col]);
                bf[nt][1] = f2tf32(Bs[(kk + 4) * 136 + col]);
            }
#pragma unroll
            for (int mt = 0; mt < 4; mt++)
#pragma unroll
                for (int nt = 0; nt < 4; nt++)
                    mma8(acc[mt][nt], af[mt], bf[nt]);
        }
        __syncthreads();
    }

#pragma unroll
    for (int mt = 0; mt < 4; mt++) {
        const int row = m0 + wm + mt * 16 + gid;
#pragma unroll
        for (int nt = 0; nt < 4; nt++) {
            const int col = n0 + wn + nt * 8 + tig * 2;
            float b0v = 0.f, b1v = 0.f;
            if (bias) { b0v = bias[col]; b1v = bias[col + 1]; }
#pragma unroll
            for (int half = 0; half < 2; half++) {
                float2 v;
                v.x = acc[mt][nt][half * 2 + 0] * alpha + b0v;
                v.y = acc[mt][nt][half * 2 + 1] * alpha + b1v;
                *reinterpret_cast<float2*>(C + (size_t)(row + half * 8) * ldc_ + col) = v;
            }
        }
    }
}

// ---------------- softmax, L = 4096 -------------------------------------------
__global__ __launch_bounds__(256) void softmax4096_kernel(float* __restrict__ X)
{
    float* x = X + (size_t)blockIdx.x * 4096;
    const int t = threadIdx.x;
    float v[16];
    float m = -1e30f;
#pragma unroll
    for (int i = 0; i < 16; i++) { v[i] = x[t + i * 256]; m = fmaxf(m, v[i]); }
    __shared__ float red[8];
    const int lane = t & 31, w = t >> 5;
#pragma unroll
    for (int o = 16; o > 0; o >>= 1) m = fmaxf(m, __shfl_xor_sync(0xffffffffu, m, o));
    if (lane == 0) red[w] = m;
    __syncthreads();
    float bm = red[0];
#pragma unroll
    for (int i = 1; i < 8; i++) bm = fmaxf(bm, red[i]);
    float s = 0.f;
#pragma unroll
    for (int i = 0; i < 16; i++) { v[i] = __expf(v[i] - bm); s += v[i]; }
#pragma unroll
    for (int o = 16; o > 0; o >>= 1) s += __shfl_xor_sync(0xffffffffu, s, o);
    __syncthreads();
    if (lane == 0) red[w] = s;
    __syncthreads();
    float bs = 0.f;
#pragma unroll
    for (int i = 0; i < 8; i++) bs += red[i];
    const float inv = 1.0f / bs;
#pragma unroll
    for (int i = 0; i < 16; i++) x[t + i * 256] = v[i] * inv;
}

// ---------------- softmax, L = 256 --------------------------------------------
__global__ __launch_bounds__(256) void softmax256_kernel(float* __restrict__ X)
{
    const int lane = threadIdx.x & 31;
    const int w    = threadIdx.x >> 5;
    float* x = X + ((size_t)blockIdx.x * 8 + w) * 256;
    float v[8];
    float m = -1e30f;
#pragma unroll
    for (int i = 0; i < 8; i++) { v[i] = x[lane + i * 32]; m = fmaxf(m, v[i]); }
#pragma unroll
    for (int o = 16; o > 0; o >>= 1) m = fmaxf(m, __shfl_xor_sync(0xffffffffu, m, o));
    float s = 0.f;
#pragma unroll
    for (int i = 0; i < 8; i++) { v[i] = __expf(v[i] - m); s += v[i]; }
#pragma unroll
    for (int o = 16; o > 0; o >>= 1) s += __shfl_xor_sync(0xffffffffu, s, o);
    const float inv = 1.0f / s;
#pragma unroll
    for (int i = 0; i < 8; i++) x[lane + i * 32] = v[i] * inv;
}

// ---------------- residual add + LayerNorm ------------------------------------
template<int VPT>
__global__ __launch_bounds__(256) void add_ln_kernel(
    const float* __restrict__ R, const float* __restrict__ X,
    const float* __restrict__ g, const float* __restrict__ bta,
    float* __restrict__ Y, int D)
{
    const size_t row = blockIdx.x;
    const float* r = R + row * D;
    const float* x = X + row * D;
    float* y = Y + row * D;
    const int t = threadIdx.x;
    float v[VPT];
    float s = 0.f, sq = 0.f;
#pragma unroll
    for (int i = 0; i < VPT; i++) {
        const int c = t + i * 256;
        v[i] = r[c] + x[c];
        s += v[i]; sq += v[i] * v[i];
    }
    const int lane = t & 31, w = t >> 5;
#pragma unroll
    for (int o = 16; o > 0; o >>= 1) {
        s  += __shfl_xor_sync(0xffffffffu, s, o);
        sq += __shfl_xor_sync(0xffffffffu, sq, o);
    }
    __shared__ float rs[8], rq[8];
    if (lane == 0) { rs[w] = s; rq[w] = sq; }
    __syncthreads();
    s = 0.f; sq = 0.f;
#pragma unroll
    for (int i = 0; i < 8; i++) { s += rs[i]; sq += rq[i]; }
    const float mean = s / D;
    const float var  = sq / D - mean * mean;
    const float inv  = rsqrtf(var + 1e-5f);
#pragma unroll
    for (int i = 0; i < VPT; i++) {
        const int c = t + i * 256;
        y[c] = (v[i] - mean) * inv * g[c] + bta[c];
    }
}

// ---------------- launch --------------------------------------------------------
extern "C" void kernel_launch(void* const* d_in, const int* in_sizes, int n_in,
                              void* d_out, int out_size)
{
    const float* hidden = (const float*)d_in[0];
    const float* aux    = (const float*)d_in[1];
    const float* wq1 = (const float*)d_in[2];  const float* bq1 = (const float*)d_in[3];
    const float* wk1 = (const float*)d_in[4];  const float* bk1 = (const float*)d_in[5];
    const float* wv1 = (const float*)d_in[6];  const float* bv1 = (const float*)d_in[7];
    const float* wo1 = (const float*)d_in[8];  const float* bo1 = (const float*)d_in[9];
    const float* wq2 = (const float*)d_in[10]; const float* bq2 = (const float*)d_in[11];
    const float* wk2 = (const float*)d_in[12]; const float* bk2 = (const float*)d_in[13];
    const float* wv2 = (const float*)d_in[14]; const float* bv2 = (const float*)d_in[15];
    const float* wo2 = (const float*)d_in[16]; const float* bo2 = (const float*)d_in[17];
    const float* g_aux = (const float*)d_in[18]; const float* b_aux = (const float*)d_in[19];
    const float* g_h   = (const float*)d_in[20]; const float* b_h   = (const float*)d_in[21];

    const int SM_NN = 3 * (2560 + 2176) * 4;
    cudaFuncSetAttribute(mma_gemm_big,
        cudaFuncAttributeMaxDynamicSharedMemorySize, BG_SMEM);
    cudaFuncSetAttribute(mma_gemm_nn,
        cudaFuncAttributeMaxDynamicSharedMemorySize, SM_NN);

    float* scratch = nullptr;
    cudaGetSymbolAddress((void**)&scratch, g_scratch);
    float* q1    = scratch + 0;
    float* k1    = scratch + 1048576;
    float* v1    = scratch + 17825792;
    float* q2    = scratch + 51380224;
    float* k2    = scratch + 68157440;
    float* v2    = scratch + 69206016;
    float* ao1   = scratch + 71303168;
    float* out1  = scratch + 73400320;
    float* ao2   = scratch + 74448896;
    float* out2p = v1;  // v1 dead after attn1@v1

    float* out     = (float*)d_out;
    float* aux_out = out + (size_t)B_ * HW_ * HID_;
    float* attn2   = aux_out + (size_t)B_ * K_ * AUX_;
    float* attn1   = attn2 + (size_t)B_ * NH_ * HW_ * K_;

    // --- projections ---
    mma_gemm_big<<<dim3(2, 16),  256, BG_SMEM>>>(aux, wq1, bq1, q1,
        512, 512, 512, 512, 0, 0, 0, 0, 0, 0, 1, 1.f);
    mma_gemm_big<<<dim3(2, 256), 256, BG_SMEM>>>(hidden, wk1, bk1, k1,
        1024, 1024, 1024, 512, 0, 0, 0, 0, 0, 0, 1, 1.f);
    mma_gemm_big<<<dim3(4, 256), 256, BG_SMEM>>>(hidden, wv1, bv1, v1,
        1024, 1024, 1024, 1024, 0, 0, 0, 0, 0, 0, 1, 1.f);
    mma_gemm_big<<<dim3(2, 256), 256, BG_SMEM>>>(hidden, wq2, bq2, q2,
        1024, 1024, 1024, 512, 0, 0, 0, 0, 0, 0, 1, 1.f);

    // --- pack attention: scores (b,h): 256 x 4096, headdim 64 ---
    mma_gemm_big<<<dim3(16, 2, 64), 256, BG_SMEM>>>(q1, k1, nullptr, attn1,
        64, 512, 512, 4096,
        (long long)K_ * QK_, 64,
        (long long)HW_ * QK_, 64,
        (long long)NH_ * K_ * HW_, (long long)K_ * HW_, NH_, SCALE_);
    softmax4096_kernel<<<16384, 256>>>(attn1);
    mma_gemm_nn<<<dim3(1, 2, 64), 256, SM_NN>>>(attn1, v1, nullptr, ao1,
        256, 128, 4096, 4096, 1024, 1024,
        (long long)NH_ * K_ * HW_, (long long)K_ * HW_,
        (long long)HW_ * HID_, HD_,
        (long long)K_ * HID_, HD_, NH_, 1.f);
    mma_gemm_big<<<dim3(2, 16), 256, BG_SMEM>>>(ao1, wo1, bo1, out1,
        1024, 1024, 1024, 512, 0, 0, 0, 0, 0, 0, 1, 1.f);
    add_ln_kernel<2><<<2048, 256>>>(aux, out1, g_aux, b_aux, aux_out, 512);

    // --- unpack attention ---
    mma_gemm_big<<<dim3(2, 16), 256, BG_SMEM>>>(out1, wk2, bk2, k2,
        512, 512, 512, 512, 0, 0, 0, 0, 0, 0, 1, 1.f);
    mma_gemm_big<<<dim3(4, 16), 256, BG_SMEM>>>(out1, wv2, bv2, v2,
        512, 512, 512, 1024, 0, 0, 0, 0, 0, 0, 1, 1.f);
    mma_gemm_big<<<dim3(1, 32, 64), 256, BG_SMEM>>>(q2, k2, nullptr, attn2,
        64, 512, 512, 256,
        (long long)HW_ * QK_, 64,
        (long long)K_ * QK_, 64,
        (long long)NH_ * HW_ * K_, (long long)HW_ * K_, NH_, SCALE_);
    softmax256_kernel<<<32768, 256>>>(attn2);
    mma_gemm_nn<<<dim3(1, 32, 64), 256, SM_NN>>>(attn2, v2, nullptr, ao2,
        4096, 128, 256, 256, 1024, 1024,
        (long long)NH_ * HW_ * K_, (long long)HW_ * K_,
        (long long)K_ * HID_, HD_,
        (long long)HW_ * HID_, HD_, NH_, 1.f);
    mma_gemm_big<<<dim3(4, 256), 256, BG_SMEM>>>(ao2, wo2, bo2, out2p,
        1024, 1024, 1024, 1024, 0, 0, 0, 0, 0, 0, 1, 1.f);
    add_ln_kernel<4><<<32768, 256>>>(hidden, out2p, g_h, b_h, out, 1024);
}

// round 7
// speedup vs baseline: 1.0289x; 1.0289x over previous
#include <cuda_runtime.h>
#include <math.h>
#include <stdint.h>

#define B_    8
#define HW_   4096
#define K_    256
#define HID_  1024
#define AUX_  512
#define QK_   512
#define NH_   8
#define HD_   128
#define SCALE_ 0.08838834764831845f   // 1/sqrt(128)

__device__ float g_scratch[108003328];

// ---------------- helpers -----------------------------------------------------
__device__ __forceinline__ uint32_t f2tf32(float f) {
    uint32_t u;
    asm("cvt.rna.tf32.f32 %0, %1;" : "=r"(u) : "f"(f));
    return u;
}
__device__ __forceinline__ void mma8(float* c, const uint32_t* a, const uint32_t* b) {
    asm volatile(
        "mma.sync.aligned.m16n8k8.row.col.f32.tf32.tf32.f32 "
        "{%0,%1,%2,%3}, {%4,%5,%6,%7}, {%8,%9}, {%0,%1,%2,%3};"
        : "+f"(c[0]), "+f"(c[1]), "+f"(c[2]), "+f"(c[3])
        : "r"(a[0]), "r"(a[1]), "r"(a[2]), "r"(a[3]), "r"(b[0]), "r"(b[1]));
}
__device__ __forceinline__ void cp16(void* s, const void* g) {
    uint32_t sa = (uint32_t)__cvta_generic_to_shared(s);
    asm volatile("cp.async.cg.shared.global [%0], [%1], 16;" :: "r"(sa), "l"(g));
}
__device__ __forceinline__ void barg(int id) {
    asm volatile("bar.sync %0, %1;" :: "r"(id), "r"(128) : "memory");
}

// ======== TRANSB GEMM, warpgroup-split: C[M,N] = alpha*A[M,K]*B[N,K]^T + bias =
// CTA tile 128x128 split into TWO independent 128-thread groups, each 128x64,
// own smem (A copy + B half), own cp.async groups, named barriers -> groups
// free-run against each other (4 independent groups/SM at 2 CTAs/SM).
// Warp tile 64x32 (as R2). BK=16, 2-stage. M%128==0, N%128==0, K%16==0, K>=32.
#define WG_ASTG (128 * 20)
#define WG_BSTG (64 * 20)
#define WG_GRP  (2 * (WG_ASTG + WG_BSTG))     // floats per group (2 stages)
#define WG_SMEM (2 * WG_GRP * 4)              // 61440 bytes per CTA

__global__ __launch_bounds__(256, 2) void mma_gemm_t(
    const float* __restrict__ A, const float* __restrict__ Bm,
    const float* __restrict__ bias, float* __restrict__ C,
    int Kd, int lda, int ldb, int ldc_,
    long long sAb, long long sAh, long long sBb, long long sBh,
    long long sCb, long long sCh, int nh, float alpha)
{
    extern __shared__ float sm[];

    const int z  = blockIdx.z;
    const int bb = z / nh, hh = z - bb * nh;
    A  += bb * sAb + hh * sAh;
    Bm += bb * sBb + hh * sBh;
    C  += bb * sCb + hh * sCh;

    const int t    = threadIdx.x;
    const int lane = t & 31;
    const int warp = t >> 5;
    const int g    = warp >> 2;          // warpgroup 0/1
    const int wt   = t & 127;            // thread within group
    const int gw   = warp & 3;           // warp within group

    const int m0 = blockIdx.y * 128;
    const int n0 = blockIdx.x * 128 + g * 64;   // group's 64-col slice

    float* gsm = sm + g * WG_GRP;
    float* As0 = gsm;
    float* As1 = gsm + WG_ASTG;
    float* Bs0 = gsm + 2 * WG_ASTG;
    float* Bs1 = gsm + 2 * WG_ASTG + WG_BSTG;

    const int wm  = (gw >> 1) * 64;      // 2 warps in M
    const int wn  = (gw & 1) * 32;       // 2 warps in N (within 64)
    const int gid = lane >> 2;
    const int tig = lane & 3;

    float acc[4][4][4];
#pragma unroll
    for (int i = 0; i < 4; i++)
#pragma unroll
        for (int j = 0; j < 4; j++)
#pragma unroll
            for (int r = 0; r < 4; r++) acc[i][j][r] = 0.f;

    auto loadA = [&](float* As, int k0) {
#pragma unroll
        for (int i = 0; i < 4; i++) {    // 128 rows x 4 16B-chunks = 512 chunks
            int c = wt + i * 128;
            int row = c >> 2, off = (c & 3) * 4;
            cp16(&As[row * 20 + off], A + (size_t)(m0 + row) * lda + k0 + off);
        }
    };
    auto loadB = [&](float* Bs, int k0) {
#pragma unroll
        for (int i = 0; i < 2; i++) {    // 64 rows x 4 chunks = 256 chunks
            int c = wt + i * 128;
            int row = c >> 2, off = (c & 3) * 4;
            cp16(&Bs[row * 20 + off], Bm + (size_t)(n0 + row) * ldb + k0 + off);
        }
    };

    const int nchunk = Kd >> 4;          // >= 2 for all our shapes (K >= 64)
    loadA(As0, 0);  loadB(Bs0, 0);
    asm volatile("cp.async.commit_group;");
    loadA(As1, 16); loadB(Bs1, 16);
    asm volatile("cp.async.commit_group;");

    const int bid = g + 1;               // named barriers 1 and 2 (0 reserved)

    for (int ck = 0; ck < nchunk; ck++) {
        asm volatile("cp.async.wait_group 1;");
        barg(bid);

        const float* As = (ck & 1) ? As1 : Bs0 - WG_ASTG;  // == As0/As1
        const float* Bs = (ck & 1) ? Bs1 : Bs0;
        As = (ck & 1) ? As1 : As0;
#pragma unroll
        for (int k8 = 0; k8 < 16; k8 += 8) {
            uint32_t af[4][4], bf[4][2];
            const int kk = k8 + tig;
#pragma unroll
            for (int mt = 0; mt < 4; mt++) {
                const int r = wm + mt * 16 + gid;
                af[mt][0] = f2tf32(As[r * 20 + kk]);
                af[mt][1] = f2tf32(As[(r + 8) * 20 + kk]);
                af[mt][2] = f2tf32(As[r * 20 + kk + 4]);
                af[mt][3] = f2tf32(As[(r + 8) * 20 + kk + 4]);
            }
#pragma unroll
            for (int nt = 0; nt < 4; nt++) {
                const int col = wn + nt * 8 + gid;           // 0..63 in group slice
                bf[nt][0] = f2tf32(Bs[col * 20 + kk]);
                bf[nt][1] = f2tf32(Bs[col * 20 + kk + 4]);
            }
#pragma unroll
            for (int mt = 0; mt < 4; mt++)
#pragma unroll
                for (int nt = 0; nt < 4; nt++)
                    mma8(acc[mt][nt], af[mt], bf[nt]);
        }
        barg(bid);
        if (ck + 2 < nchunk) {
            float* Asn = (ck & 1) ? As1 : As0;
            float* Bsn = (ck & 1) ? Bs1 : Bs0;
            loadA(Asn, (ck + 2) << 4);
            loadB(Bsn, (ck + 2) << 4);
        }
        asm volatile("cp.async.commit_group;");
    }

#pragma unroll
    for (int mt = 0; mt < 4; mt++) {
        const int row = m0 + wm + mt * 16 + gid;
#pragma unroll
        for (int nt = 0; nt < 4; nt++) {
            const int col = n0 + wn + nt * 8 + tig * 2;
            float b0v = 0.f, b1v = 0.f;
            if (bias) { b0v = bias[col]; b1v = bias[col + 1]; }
#pragma unroll
            for (int half = 0; half < 2; half++) {
                float2 v;
                v.x = acc[mt][nt][half * 2 + 0] * alpha + b0v;
                v.y = acc[mt][nt][half * 2 + 1] * alpha + b1v;
                *reinterpret_cast<float2*>(C + (size_t)(row + half * 8) * ldc_ + col) = v;
            }
        }
    }
}

// ---------------- NN GEMM (attn @ V), proven 128x128 3-stage ------------------
__global__ __launch_bounds__(256) void mma_gemm_nn(
    const float* __restrict__ A, const float* __restrict__ Bm,
    const float* __restrict__ bias, float* __restrict__ C,
    int M, int N, int Kd, int lda, int ldb, int ldc_,
    long long sAb, long long sAh, long long sBb, long long sBh,
    long long sCb, long long sCh, int nh, float alpha)
{
    constexpr int LDA_S = 20;
    constexpr int ASTG  = 128 * LDA_S;
    constexpr int BSTG  = 16 * 136;
    extern __shared__ float sm[];
    float* AsB = sm;
    float* BsB = sm + 3 * ASTG;

    const int z  = blockIdx.z;
    const int bb = z / nh, hh = z - bb * nh;
    A  += bb * sAb + hh * sAh;
    Bm += bb * sBb + hh * sBh;
    C  += bb * sCb + hh * sCh;

    const int m0   = blockIdx.y * 128;
    const int n0   = blockIdx.x * 128;
    const int t    = threadIdx.x;
    const int lane = t & 31;
    const int warp = t >> 5;
    const int wm   = (warp >> 2) * 64;
    const int wn   = (warp & 3) * 32;
    const int gid  = lane >> 2;
    const int tig  = lane & 3;

    float acc[4][4][4];
#pragma unroll
    for (int i = 0; i < 4; i++)
#pragma unroll
        for (int j = 0; j < 4; j++)
#pragma unroll
            for (int r = 0; r < 4; r++) acc[i][j][r] = 0.f;

    auto loadA = [&](int s, int k0) {
        float* As = AsB + s * ASTG;
#pragma unroll
        for (int i = 0; i < 2; i++) {
            int c = t + i * 256;
            int row = c >> 2, off = (c & 3) * 4;
            cp16(&As[row * LDA_S + off], A + (size_t)(m0 + row) * lda + k0 + off);
        }
    };
    auto loadB = [&](int s, int k0) {
        float* Bs = BsB + s * BSTG;
#pragma unroll
        for (int i = 0; i < 2; i++) {
            int c = t + i * 256;
            int row = c >> 5, off = (c & 31) * 4;
            cp16(&Bs[row * 136 + off], Bm + (size_t)(k0 + row) * ldb + n0 + off);
        }
    };

    const int nchunk = Kd >> 4;
    loadA(0, 0); loadB(0, 0);
    asm volatile("cp.async.commit_group;");
    if (nchunk > 1) { loadA(1, 16); loadB(1, 16); }
    asm volatile("cp.async.commit_group;");

    for (int ck = 0; ck < nchunk; ck++) {
        asm volatile("cp.async.wait_group 1;");
        __syncthreads();
        if (ck + 2 < nchunk) {
            const int s2 = (ck + 2) % 3;
            loadA(s2, (ck + 2) << 4);
            loadB(s2, (ck + 2) << 4);
        }
        asm volatile("cp.async.commit_group;");

        const int s = ck % 3;
        const float* As = AsB + s * ASTG;
        const float* Bs = BsB + s * BSTG;
#pragma unroll
        for (int k8 = 0; k8 < 16; k8 += 8) {
            uint32_t af[4][4], bf[4][2];
            const int kk = k8 + tig;
#pragma unroll
            for (int mt = 0; mt < 4; mt++) {
                const int r = wm + mt * 16 + gid;
                af[mt][0] = f2tf32(As[r * LDA_S + kk]);
                af[mt][1] = f2tf32(As[(r + 8) * LDA_S + kk]);
                af[mt][2] = f2tf32(As[r * LDA_S + kk + 4]);
                af[mt][3] = f2tf32(As[(r + 8) * LDA_S + kk + 4]);
            }
#pragma unroll
            for (int nt = 0; nt < 4; nt++) {
                const int col = wn + nt * 8 + gid;
                bf[nt][0] = f2tf32(Bs[kk * 136 + col]);
                bf[nt][1] = f2tf32(Bs[(kk + 4) * 136 + col]);
            }
#pragma unroll
            for (int mt = 0; mt < 4; mt++)
#pragma unroll
                for (int nt = 0; nt < 4; nt++)
                    mma8(acc[mt][nt], af[mt], bf[nt]);
        }
        __syncthreads();
    }

#pragma unroll
    for (int mt = 0; mt < 4; mt++) {
        const int row = m0 + wm + mt * 16 + gid;
#pragma unroll
        for (int nt = 0; nt < 4; nt++) {
            const int col = n0 + wn + nt * 8 + tig * 2;
            float b0v = 0.f, b1v = 0.f;
            if (bias) { b0v = bias[col]; b1v = bias[col + 1]; }
#pragma unroll
            for (int half = 0; half < 2; half++) {
                float2 v;
                v.x = acc[mt][nt][half * 2 + 0] * alpha + b0v;
                v.y = acc[mt][nt][half * 2 + 1] * alpha + b1v;
                *reinterpret_cast<float2*>(C + (size_t)(row + half * 8) * ldc_ + col) = v;
            }
        }
    }
}

// ---------------- softmax, L = 4096 -------------------------------------------
__global__ __launch_bounds__(256) void softmax4096_kernel(float* __restrict__ X)
{
    float* x = X + (size_t)blockIdx.x * 4096;
    const int t = threadIdx.x;
    float v[16];
    float m = -1e30f;
#pragma unroll
    for (int i = 0; i < 16; i++) { v[i] = x[t + i * 256]; m = fmaxf(m, v[i]); }
    __shared__ float red[8];
    const int lane = t & 31, w = t >> 5;
#pragma unroll
    for (int o = 16; o > 0; o >>= 1) m = fmaxf(m, __shfl_xor_sync(0xffffffffu, m, o));
    if (lane == 0) red[w] = m;
    __syncthreads();
    float bm = red[0];
#pragma unroll
    for (int i = 1; i < 8; i++) bm = fmaxf(bm, red[i]);
    float s = 0.f;
#pragma unroll
    for (int i = 0; i < 16; i++) { v[i] = __expf(v[i] - bm); s += v[i]; }
#pragma unroll
    for (int o = 16; o > 0; o >>= 1) s += __shfl_xor_sync(0xffffffffu, s, o);
    __syncthreads();
    if (lane == 0) red[w] = s;
    __syncthreads();
    float bs = 0.f;
#pragma unroll
    for (int i = 0; i < 8; i++) bs += red[i];
    const float inv = 1.0f / bs;
#pragma unroll
    for (int i = 0; i < 16; i++) x[t + i * 256] = v[i] * inv;
}

// ---------------- softmax, L = 256 --------------------------------------------
__global__ __launch_bounds__(256) void softmax256_kernel(float* __restrict__ X)
{
    const int lane = threadIdx.x & 31;
    const int w    = threadIdx.x >> 5;
    float* x = X + ((size_t)blockIdx.x * 8 + w) * 256;
    float v[8];
    float m = -1e30f;
#pragma unroll
    for (int i = 0; i < 8; i++) { v[i] = x[lane + i * 32]; m = fmaxf(m, v[i]); }
#pragma unroll
    for (int o = 16; o > 0; o >>= 1) m = fmaxf(m, __shfl_xor_sync(0xffffffffu, m, o));
    float s = 0.f;
#pragma unroll
    for (int i = 0; i < 8; i++) { v[i] = __expf(v[i] - m); s += v[i]; }
#pragma unroll
    for (int o = 16; o > 0; o >>= 1) s += __shfl_xor_sync(0xffffffffu, s, o);
    const float inv = 1.0f / s;
#pragma unroll
    for (int i = 0; i < 8; i++) x[lane + i * 32] = v[i] * inv;
}

// ---------------- residual add + LayerNorm ------------------------------------
template<int VPT>
__global__ __launch_bounds__(256) void add_ln_kernel(
    const float* __restrict__ R, const float* __restrict__ X,
    const float* __restrict__ g, const float* __restrict__ bta,
    float* __restrict__ Y, int D)
{
    const size_t row = blockIdx.x;
    const float* r = R + row * D;
    const float* x = X + row * D;
    float* y = Y + row * D;
    const int t = threadIdx.x;
    float v[VPT];
    float s = 0.f, sq = 0.f;
#pragma unroll
    for (int i = 0; i < VPT; i++) {
        const int c = t + i * 256;
        v[i] = r[c] + x[c];
        s += v[i]; sq += v[i] * v[i];
    }
    const int lane = t & 31, w = t >> 5;
#pragma unroll
    for (int o = 16; o > 0; o >>= 1) {
        s  += __shfl_xor_sync(0xffffffffu, s, o);
        sq += __shfl_xor_sync(0xffffffffu, sq, o);
    }
    __shared__ float rs[8], rq[8];
    if (lane == 0) { rs[w] = s; rq[w] = sq; }
    __syncthreads();
    s = 0.f; sq = 0.f;
#pragma unroll
    for (int i = 0; i < 8; i++) { s += rs[i]; sq += rq[i]; }
    const float mean = s / D;
    const float var  = sq / D - mean * mean;
    const float inv  = rsqrtf(var + 1e-5f);
#pragma unroll
    for (int i = 0; i < VPT; i++) {
        const int c = t + i * 256;
        y[c] = (v[i] - mean) * inv * g[c] + bta[c];
    }
}

// ---------------- launch --------------------------------------------------------
extern "C" void kernel_launch(void* const* d_in, const int* in_sizes, int n_in,
                              void* d_out, int out_size)
{
    const float* hidden = (const float*)d_in[0];
    const float* aux    = (const float*)d_in[1];
    const float* wq1 = (const float*)d_in[2];  const float* bq1 = (const float*)d_in[3];
    const float* wk1 = (const float*)d_in[4];  const float* bk1 = (const float*)d_in[5];
    const float* wv1 = (const float*)d_in[6];  const float* bv1 = (const float*)d_in[7];
    const float* wo1 = (const float*)d_in[8];  const float* bo1 = (const float*)d_in[9];
    const float* wq2 = (const float*)d_in[10]; const float* bq2 = (const float*)d_in[11];
    const float* wk2 = (const float*)d_in[12]; const float* bk2 = (const float*)d_in[13];
    const float* wv2 = (const float*)d_in[14]; const float* bv2 = (const float*)d_in[15];
    const float* wo2 = (const float*)d_in[16]; const float* bo2 = (const float*)d_in[17];
    const float* g_aux = (const float*)d_in[18]; const float* b_aux = (const float*)d_in[19];
    const float* g_h   = (const float*)d_in[20]; const float* b_h   = (const float*)d_in[21];

    const int SM_NN = 3 * (2560 + 2176) * 4;
    cudaFuncSetAttribute(mma_gemm_t,
        cudaFuncAttributeMaxDynamicSharedMemorySize, WG_SMEM);
    cudaFuncSetAttribute(mma_gemm_nn,
        cudaFuncAttributeMaxDynamicSharedMemorySize, SM_NN);

    float* scratch = nullptr;
    cudaGetSymbolAddress((void**)&scratch, g_scratch);
    float* q1    = scratch + 0;
    float* k1    = scratch + 1048576;
    float* v1    = scratch + 17825792;
    float* q2    = scratch + 51380224;
    float* k2    = scratch + 68157440;
    float* v2    = scratch + 69206016;
    float* ao1   = scratch + 71303168;
    float* out1  = scratch + 73400320;
    float* ao2   = scratch + 74448896;
    float* out2p = v1;  // v1 dead after attn1@v1

    float* out     = (float*)d_out;
    float* aux_out = out + (size_t)B_ * HW_ * HID_;
    float* attn2   = aux_out + (size_t)B_ * K_ * AUX_;
    float* attn1   = attn2 + (size_t)B_ * NH_ * HW_ * K_;

    // --- projections ---
    mma_gemm_t<<<dim3(4, 16),  256, WG_SMEM>>>(aux, wq1, bq1, q1,
        512, 512, 512, 512, 0, 0, 0, 0, 0, 0, 1, 1.f);
    mma_gemm_t<<<dim3(4, 256), 256, WG_SMEM>>>(hidden, wk1, bk1, k1,
        1024, 1024, 1024, 512, 0, 0, 0, 0, 0, 0, 1, 1.f);
    mma_gemm_t<<<dim3(8, 256), 256, WG_SMEM>>>(hidden, wv1, bv1, v1,
        1024, 1024, 1024, 1024, 0, 0, 0, 0, 0, 0, 1, 1.f);
    mma_gemm_t<<<dim3(4, 256), 256, WG_SMEM>>>(hidden, wq2, bq2, q2,
        1024, 1024, 1024, 512, 0, 0, 0, 0, 0, 0, 1, 1.f);

    // --- pack attention: scores (b,h): 256 x 4096, headdim 64 ---
    mma_gemm_t<<<dim3(32, 2, 64), 256, WG_SMEM>>>(q1, k1, nullptr, attn1,
        64, 512, 512, 4096,
        (long long)K_ * QK_, 64,
        (long long)HW_ * QK_, 64,
        (long long)NH_ * K_ * HW_, (long long)K_ * HW_, NH_, SCALE_);
    softmax4096_kernel<<<16384, 256>>>(attn1);
    mma_gemm_nn<<<dim3(1, 2, 64), 256, SM_NN>>>(attn1, v1, nullptr, ao1,
        256, 128, 4096, 4096, 1024, 1024,
        (long long)NH_ * K_ * HW_, (long long)K_ * HW_,
        (long long)HW_ * HID_, HD_,
        (long long)K_ * HID_, HD_, NH_, 1.f);
    mma_gemm_t<<<dim3(4, 16), 256, WG_SMEM>>>(ao1, wo1, bo1, out1,
        1024, 1024, 1024, 512, 0, 0, 0, 0, 0, 0, 1, 1.f);
    add_ln_kernel<2><<<2048, 256>>>(aux, out1, g_aux, b_aux, aux_out, 512);

    // --- unpack attention ---
    mma_gemm_t<<<dim3(4, 16), 256, WG_SMEM>>>(out1, wk2, bk2, k2,
        512, 512, 512, 512, 0, 0, 0, 0, 0, 0, 1, 1.f);
    mma_gemm_t<<<dim3(8, 16), 256, WG_SMEM>>>(out1, wv2, bv2, v2,
        512, 512, 512, 1024, 0, 0, 0, 0, 0, 0, 1, 1.f);
    mma_gemm_t<<<dim3(2, 32, 64), 256, WG_SMEM>>>(q2, k2, nullptr, attn2,
        64, 512, 512, 256,
        (long long)HW_ * QK_, 64,
        (long long)K_ * QK_, 64,
        (long long)NH_ * HW_ * K_, (long long)HW_ * K_, NH_, SCALE_);
    softmax256_kernel<<<32768, 256>>>(attn2);
    mma_gemm_nn<<<dim3(1, 32, 64), 256, SM_NN>>>(attn2, v2, nullptr, ao2,
        4096, 128, 256, 256, 1024, 1024,
        (long long)NH_ * HW_ * K_, (long long)HW_ * K_,
        (long long)K_ * HID_, HD_,
        (long long)HW_ * HID_, HD_, NH_, 1.f);
    mma_gemm_t<<<dim3(8, 256), 256, WG_SMEM>>>(ao2, wo2, bo2, out2p,
        1024, 1024, 1024, 1024, 0, 0, 0, 0, 0, 0, 1, 1.f);
    add_ln_kernel<4><<<32768, 256>>>(hidden, out2p, g_h, b_h, out, 1024);
}

// round 8
// speedup vs baseline: 1.7528x; 1.7036x over previous
#include <cuda_runtime.h>
#include <cuda_fp16.h>
#include <math.h>
#include <stdint.h>

#define B_    8
#define HW_   4096
#define K_    256
#define HID_  1024
#define AUX_  512
#define QK_   512
#define NH_   8
#define HD_   128
#define SCALE_ 0.08838834764831845f   // 1/sqrt(128)

// scratch: fp32 region then fp16 region (see offsets in kernel_launch)
__device__ float g_scratch[175374336];

// ---------------- helpers -----------------------------------------------------
__device__ __forceinline__ void cp16(void* s, const void* g) {
    uint32_t sa = (uint32_t)__cvta_generic_to_shared(s);
    asm volatile("cp.async.cg.shared.global [%0], [%1], 16;" :: "r"(sa), "l"(g));
}
__device__ __forceinline__ void ldsm4(uint32_t* r, uint32_t a) {
    asm volatile("ldmatrix.sync.aligned.m8n8.x4.shared.b16 {%0,%1,%2,%3}, [%4];"
        : "=r"(r[0]), "=r"(r[1]), "=r"(r[2]), "=r"(r[3]) : "r"(a));
}
__device__ __forceinline__ void ldsm4t(uint32_t* r, uint32_t a) {
    asm volatile("ldmatrix.sync.aligned.m8n8.x4.trans.shared.b16 {%0,%1,%2,%3}, [%4];"
        : "=r"(r[0]), "=r"(r[1]), "=r"(r[2]), "=r"(r[3]) : "r"(a));
}
__device__ __forceinline__ void mma16(float* c, const uint32_t* a, const uint32_t* b) {
    asm volatile(
        "mma.sync.aligned.m16n8k16.row.col.f32.f16.f16.f32 "
        "{%0,%1,%2,%3}, {%4,%5,%6,%7}, {%8,%9}, {%0,%1,%2,%3};"
        : "+f"(c[0]), "+f"(c[1]), "+f"(c[2]), "+f"(c[3])
        : "r"(a[0]), "r"(a[1]), "r"(a[2]), "r"(a[3]), "r"(b[0]), "r"(b[1]));
}

// ---------------- fp32 -> fp16 conversion pre-pass ----------------------------
__global__ __launch_bounds__(256) void cvt_kernel(const float* __restrict__ x,
                                                  __half* __restrict__ y)
{
    const size_t i = ((size_t)blockIdx.x * 256 + threadIdx.x) * 8;
    float4 a = *reinterpret_cast<const float4*>(x + i);
    float4 b = *reinterpret_cast<const float4*>(x + i + 4);
    __half2 h0 = __floats2half2_rn(a.x, a.y);
    __half2 h1 = __floats2half2_rn(a.z, a.w);
    __half2 h2 = __floats2half2_rn(b.x, b.y);
    __half2 h3 = __floats2half2_rn(b.z, b.w);
    uint4 o;
    o.x = *reinterpret_cast<uint32_t*>(&h0);
    o.y = *reinterpret_cast<uint32_t*>(&h1);
    o.z = *reinterpret_cast<uint32_t*>(&h2);
    o.w = *reinterpret_cast<uint32_t*>(&h3);
    *reinterpret_cast<uint4*>(y + i) = o;
}

// ======== fp16 TRANSB GEMM: C[M,N] = alpha*A[M,K]*B[N,K]^T + bias =============
// Tile 128x128, BK=32, 3-stage cp.async ring, 8 warps 64x32, ldmatrix + m16n8k16.
#define HT_SA   40                    // halfs per smem row (32 + 8 pad)
#define HT_STG  (128 * HT_SA)         // halfs per operand stage
#define HT_PAIR (2 * HT_STG)
#define HT_SMEM (3 * HT_PAIR * 2)     // 61440 bytes

__global__ __launch_bounds__(256, 2) void hgemm_t(
    const __half* __restrict__ A, const __half* __restrict__ Bm,
    const float* __restrict__ bias, float* __restrict__ Cf, __half* __restrict__ Ch,
    int Kd, int lda, int ldb, int ldc,
    long long sAb, long long sAh, long long sBb, long long sBh,
    long long sCb, long long sCh, int nh, float alpha)
{
    extern __shared__ __half hsm[];
    const int z = blockIdx.z, bb = z / nh, hh = z - bb * nh;
    A  += bb * sAb + hh * sAh;
    Bm += bb * sBb + hh * sBh;
    const long long cO = bb * sCb + hh * sCh;

    const int m0 = blockIdx.y * 128, n0 = blockIdx.x * 128;
    const int t = threadIdx.x, lane = t & 31, warp = t >> 5;
    const int wm = (warp >> 2) * 64, wn = (warp & 3) * 32;
    const uint32_t smb = (uint32_t)__cvta_generic_to_shared(hsm);

    float acc[4][4][4];
#pragma unroll
    for (int i = 0; i < 4; i++)
#pragma unroll
        for (int j = 0; j < 4; j++)
#pragma unroll
            for (int r = 0; r < 4; r++) acc[i][j][r] = 0.f;

    auto fill = [&](int s, int ck) {
        __half* Sa = hsm + s * HT_PAIR;
        __half* Sb = Sa + HT_STG;
        const int k0 = ck * 32;
#pragma unroll
        for (int i = 0; i < 2; i++) {
            int c = t + i * 256, row = c >> 2, o = (c & 3) * 8;
            cp16(&Sa[row * HT_SA + o], A + (size_t)(m0 + row) * lda + k0 + o);
        }
#pragma unroll
        for (int i = 0; i < 2; i++) {
            int c = t + i * 256, row = c >> 2, o = (c & 3) * 8;
            cp16(&Sb[row * HT_SA + o], Bm + (size_t)(n0 + row) * ldb + k0 + o);
        }
    };

    const int nchunk = Kd >> 5;
    fill(0, 0);
    asm volatile("cp.async.commit_group;");
    if (nchunk > 1) fill(1, 1);
    asm volatile("cp.async.commit_group;");

    const int lrow = lane & 15;
    const int lcol = (lane >> 4) * 8;

    for (int ck = 0; ck < nchunk; ck++) {
        asm volatile("cp.async.wait_group 1;");
        __syncthreads();
        if (ck + 2 < nchunk) fill((ck + 2) % 3, ck + 2);
        asm volatile("cp.async.commit_group;");

        const uint32_t sA = smb + (uint32_t)((ck % 3) * HT_PAIR) * 2;
        const uint32_t sB = sA + HT_STG * 2;
#pragma unroll
        for (int ks = 0; ks < 2; ks++) {
            uint32_t af[4][4], bq[2][4];
#pragma unroll
            for (int mt = 0; mt < 4; mt++)
                ldsm4(af[mt], sA + 2 * ((wm + mt * 16 + lrow) * HT_SA + ks * 16 + lcol));
#pragma unroll
            for (int p = 0; p < 2; p++)
                ldsm4(bq[p], sB + 2 * ((wn + p * 16 + lrow) * HT_SA + ks * 16 + lcol));
#pragma unroll
            for (int mt = 0; mt < 4; mt++)
#pragma unroll
                for (int p = 0; p < 2; p++) {
                    uint32_t b0[2] = { bq[p][0], bq[p][2] };   // n-tile 2p
                    uint32_t b1[2] = { bq[p][1], bq[p][3] };   // n-tile 2p+1
                    mma16(acc[mt][2 * p],     af[mt], b0);
                    mma16(acc[mt][2 * p + 1], af[mt], b1);
                }
        }
        __syncthreads();
    }

    const int gid = lane >> 2, tig = lane & 3;
#pragma unroll
    for (int mt = 0; mt < 4; mt++) {
        const int row = m0 + wm + mt * 16 + gid;
#pragma unroll
        for (int nt = 0; nt < 4; nt++) {
            const int col = n0 + wn + nt * 8 + tig * 2;
            float b0v = 0.f, b1v = 0.f;
            if (bias) { b0v = bias[col]; b1v = bias[col + 1]; }
#pragma unroll
            for (int h = 0; h < 2; h++) {
                float2 v;
                v.x = acc[mt][nt][h * 2 + 0] * alpha + b0v;
                v.y = acc[mt][nt][h * 2 + 1] * alpha + b1v;
                const long long idx = cO + (long long)(row + h * 8) * ldc + col;
                if (Cf) *reinterpret_cast<float2*>(Cf + idx) = v;
                if (Ch) {
                    __half2 hv = __floats2half2_rn(v.x, v.y);
                    *reinterpret_cast<__half2*>(Ch + idx) = hv;
                }
            }
        }
    }
}

// ======== fp16 NN GEMM (attn @ V): A[M,K] k-contig, B[K,N] n-contig ===========
#define HN_SB   136
#define HN_BSTG (32 * HN_SB)
#define HN_PAIR (HT_STG + HN_BSTG)
#define HN_SMEM (3 * HN_PAIR * 2)     // 56832 bytes

__global__ __launch_bounds__(256, 2) void hgemm_nn(
    const __half* __restrict__ A, const __half* __restrict__ Bm,
    float* __restrict__ Cf, __half* __restrict__ Ch,
    int Kd, int lda, int ldb, int ldc,
    long long sAb, long long sAh, long long sBb, long long sBh,
    long long sCb, long long sCh, int nh)
{
    extern __shared__ __half hsm[];
    const int z = blockIdx.z, bb = z / nh, hh = z - bb * nh;
    A  += bb * sAb + hh * sAh;
    Bm += bb * sBb + hh * sBh;
    const long long cO = bb * sCb + hh * sCh;

    const int m0 = blockIdx.y * 128, n0 = blockIdx.x * 128;
    const int t = threadIdx.x, lane = t & 31, warp = t >> 5;
    const int wm = (warp >> 2) * 64, wn = (warp & 3) * 32;
    const uint32_t smb = (uint32_t)__cvta_generic_to_shared(hsm);

    float acc[4][4][4];
#pragma unroll
    for (int i = 0; i < 4; i++)
#pragma unroll
        for (int j = 0; j < 4; j++)
#pragma unroll
            for (int r = 0; r < 4; r++) acc[i][j][r] = 0.f;

    auto fill = [&](int s, int ck) {
        __half* Sa = hsm + s * HN_PAIR;
        __half* Sb = Sa + HT_STG;
        const int k0 = ck * 32;
#pragma unroll
        for (int i = 0; i < 2; i++) {
            int c = t + i * 256, row = c >> 2, o = (c & 3) * 8;
            cp16(&Sa[row * HT_SA + o], A + (size_t)(m0 + row) * lda + k0 + o);
        }
#pragma unroll
        for (int i = 0; i < 2; i++) {
            int c = t + i * 256, row = c >> 4, o = (c & 15) * 8;
            cp16(&Sb[row * HN_SB + o], Bm + (size_t)(k0 + row) * ldb + n0 + o);
        }
    };

    const int nchunk = Kd >> 5;
    fill(0, 0);
    asm volatile("cp.async.commit_group;");
    if (nchunk > 1) fill(1, 1);
    asm volatile("cp.async.commit_group;");

    const int lrow  = lane & 15;
    const int lcol  = (lane >> 4) * 8;
    const int tkrow = ((lane >> 3) & 1) * 8 + (lane & 7);   // for trans B
    const int tncol = (lane >> 4) * 8;

    for (int ck = 0; ck < nchunk; ck++) {
        asm volatile("cp.async.wait_group 1;");
        __syncthreads();
        if (ck + 2 < nchunk) fill((ck + 2) % 3, ck + 2);
        asm volatile("cp.async.commit_group;");

        const uint32_t sA = smb + (uint32_t)((ck % 3) * HN_PAIR) * 2;
        const uint32_t sB = sA + HT_STG * 2;
#pragma unroll
        for (int ks = 0; ks < 2; ks++) {
            uint32_t af[4][4], bq[2][4];
#pragma unroll
            for (int mt = 0; mt < 4; mt++)
                ldsm4(af[mt], sA + 2 * ((wm + mt * 16 + lrow) * HT_SA + ks * 16 + lcol));
#pragma unroll
            for (int p = 0; p < 2; p++)
                ldsm4t(bq[p], sB + 2 * ((ks * 16 + tkrow) * HN_SB + wn + p * 16 + tncol));
#pragma unroll
            for (int mt = 0; mt < 4; mt++)
#pragma unroll
                for (int p = 0; p < 2; p++) {
                    uint32_t b0[2] = { bq[p][0], bq[p][1] };   // n-tile 2p
                    uint32_t b1[2] = { bq[p][2], bq[p][3] };   // n-tile 2p+1
                    mma16(acc[mt][2 * p],     af[mt], b0);
                    mma16(acc[mt][2 * p + 1], af[mt], b1);
                }
        }
        __syncthreads();
    }

    const int gid = lane >> 2, tig = lane & 3;
#pragma unroll
    for (int mt = 0; mt < 4; mt++) {
        const int row = m0 + wm + mt * 16 + gid;
#pragma unroll
        for (int nt = 0; nt < 4; nt++) {
            const int col = n0 + wn + nt * 8 + tig * 2;
#pragma unroll
            for (int h = 0; h < 2; h++) {
                float2 v;
                v.x = acc[mt][nt][h * 2 + 0];
                v.y = acc[mt][nt][h * 2 + 1];
                const long long idx = cO + (long long)(row + h * 8) * ldc + col;
                if (Cf) *reinterpret_cast<float2*>(Cf + idx) = v;
                if (Ch) {
                    __half2 hv = __floats2half2_rn(v.x, v.y);
                    *reinterpret_cast<__half2*>(Ch + idx) = hv;
                }
            }
        }
    }
}

// ---------------- softmax, L = 4096 (fp32 in-place + fp16 copy) ---------------
__global__ __launch_bounds__(256) void softmax4096_kernel(float* __restrict__ X,
                                                          __half* __restrict__ Xh)
{
    float* x = X + (size_t)blockIdx.x * 4096;
    __half* xh = Xh + (size_t)blockIdx.x * 4096;
    const int t = threadIdx.x;
    float v[16];
    float m = -1e30f;
#pragma unroll
    for (int i = 0; i < 16; i++) { v[i] = x[t + i * 256]; m = fmaxf(m, v[i]); }
    __shared__ float red[8];
    const int lane = t & 31, w = t >> 5;
#pragma unroll
    for (int o = 16; o > 0; o >>= 1) m = fmaxf(m, __shfl_xor_sync(0xffffffffu, m, o));
    if (lane == 0) red[w] = m;
    __syncthreads();
    float bm = red[0];
#pragma unroll
    for (int i = 1; i < 8; i++) bm = fmaxf(bm, red[i]);
    float s = 0.f;
#pragma unroll
    for (int i = 0; i < 16; i++) { v[i] = __expf(v[i] - bm); s += v[i]; }
#pragma unroll
    for (int o = 16; o > 0; o >>= 1) s += __shfl_xor_sync(0xffffffffu, s, o);
    __syncthreads();
    if (lane == 0) red[w] = s;
    __syncthreads();
    float bs = 0.f;
#pragma unroll
    for (int i = 0; i < 8; i++) bs += red[i];
    const float inv = 1.0f / bs;
#pragma unroll
    for (int i = 0; i < 16; i++) {
        float r = v[i] * inv;
        x[t + i * 256]  = r;
        xh[t + i * 256] = __float2half_rn(r);
    }
}

// ---------------- softmax, L = 256 --------------------------------------------
__global__ __launch_bounds__(256) void softmax256_kernel(float* __restrict__ X,
                                                         __half* __restrict__ Xh)
{
    const int lane = threadIdx.x & 31;
    const int w    = threadIdx.x >> 5;
    const size_t rb = ((size_t)blockIdx.x * 8 + w) * 256;
    float* x = X + rb;
    __half* xh = Xh + rb;
    float v[8];
    float m = -1e30f;
#pragma unroll
    for (int i = 0; i < 8; i++) { v[i] = x[lane + i * 32]; m = fmaxf(m, v[i]); }
#pragma unroll
    for (int o = 16; o > 0; o >>= 1) m = fmaxf(m, __shfl_xor_sync(0xffffffffu, m, o));
    float s = 0.f;
#pragma unroll
    for (int i = 0; i < 8; i++) { v[i] = __expf(v[i] - m); s += v[i]; }
#pragma unroll
    for (int o = 16; o > 0; o >>= 1) s += __shfl_xor_sync(0xffffffffu, s, o);
    const float inv = 1.0f / s;
#pragma unroll
    for (int i = 0; i < 8; i++) {
        float r = v[i] * inv;
        x[lane + i * 32]  = r;
        xh[lane + i * 32] = __float2half_rn(r);
    }
}

// ---------------- residual add + LayerNorm ------------------------------------
template<int VPT>
__global__ __launch_bounds__(256) void add_ln_kernel(
    const float* __restrict__ R, const float* __restrict__ X,
    const float* __restrict__ g, const float* __restrict__ bta,
    float* __restrict__ Y, int D)
{
    const size_t row = blockIdx.x;
    const float* r = R + row * D;
    const float* x = X + row * D;
    float* y = Y + row * D;
    const int t = threadIdx.x;
    float v[VPT];
    float s = 0.f, sq = 0.f;
#pragma unroll
    for (int i = 0; i < VPT; i++) {
        const int c = t + i * 256;
        v[i] = r[c] + x[c];
        s += v[i]; sq += v[i] * v[i];
    }
    const int lane = t & 31, w = t >> 5;
#pragma unroll
    for (int o = 16; o > 0; o >>= 1) {
        s  += __shfl_xor_sync(0xffffffffu, s, o);
        sq += __shfl_xor_sync(0xffffffffu, sq, o);
    }
    __shared__ float rs[8], rq[8];
    if (lane == 0) { rs[w] = s; rq[w] = sq; }
    __syncthreads();
    s = 0.f; sq = 0.f;
#pragma unroll
    for (int i = 0; i < 8; i++) { s += rs[i]; sq += rq[i]; }
    const float mean = s / D;
    const float var  = sq / D - mean * mean;
    const float inv  = rsqrtf(var + 1e-5f);
#pragma unroll
    for (int i = 0; i < VPT; i++) {
        const int c = t + i * 256;
        y[c] = (v[i] - mean) * inv * g[c] + bta[c];
    }
}

// ---------------- launch --------------------------------------------------------
extern "C" void kernel_launch(void* const* d_in, const int* in_sizes, int n_in,
                              void* d_out, int out_size)
{
    const float* hidden = (const float*)d_in[0];
    const float* aux    = (const float*)d_in[1];
    const float* wq1 = (const float*)d_in[2];  const float* bq1 = (const float*)d_in[3];
    const float* wk1 = (const float*)d_in[4];  const float* bk1 = (const float*)d_in[5];
    const float* wv1 = (const float*)d_in[6];  const float* bv1 = (const float*)d_in[7];
    const float* wo1 = (const float*)d_in[8];  const float* bo1 = (const float*)d_in[9];
    const float* wq2 = (const float*)d_in[10]; const float* bq2 = (const float*)d_in[11];
    const float* wk2 = (const float*)d_in[12]; const float* bk2 = (const float*)d_in[13];
    const float* wv2 = (const float*)d_in[14]; const float* bv2 = (const float*)d_in[15];
    const float* wo2 = (const float*)d_in[16]; const float* bo2 = (const float*)d_in[17];
    const float* g_aux = (const float*)d_in[18]; const float* b_aux = (const float*)d_in[19];
    const float* g_h   = (const float*)d_in[20]; const float* b_h   = (const float*)d_in[21];

    cudaFuncSetAttribute(hgemm_t,
        cudaFuncAttributeMaxDynamicSharedMemorySize, HT_SMEM);
    cudaFuncSetAttribute(hgemm_nn,
        cudaFuncAttributeMaxDynamicSharedMemorySize, HN_SMEM);

    float* scratch = nullptr;
    cudaGetSymbolAddress((void**)&scratch, g_scratch);

    // fp32 region
    float* out2p = scratch;                 // 33,554,432
    float* out1f = scratch + 33554432;      // 1,048,576
    // fp16 region
    __half* hb = (__half*)(scratch + 34603008);
    __half* h_h    = hb;
    __half* a_h    = hb + 33554432;
    __half* wq1h   = hb + 34603008;
    __half* wk1h   = hb + 34865152;
    __half* wv1h   = hb + 35389440;
    __half* wo1h   = hb + 36438016;
    __half* wq2h   = hb + 36962304;
    __half* wk2h   = hb + 37486592;
    __half* wv2h   = hb + 37748736;
    __half* wo2h   = hb + 38273024;
    __half* q1h    = hb + 39321600;
    __half* k1h    = hb + 40370176;
    __half* v1h    = hb + 57147392;
    __half* q2h    = hb + 90701824;
    __half* k2h    = hb + 107479040;
    __half* v2h    = hb + 108527616;
    __half* ao1h   = hb + 110624768;
    __half* ao2h   = hb + 112721920;
    __half* out1h  = hb + 146276352;
    __half* attn1h = hb + 147324928;
    __half* attn2h = hb + 214433792;

    float* out     = (float*)d_out;
    float* aux_out = out + (size_t)B_ * HW_ * HID_;
    float* attn2   = aux_out + (size_t)B_ * K_ * AUX_;
    float* attn1   = attn2 + (size_t)B_ * NH_ * HW_ * K_;

    // --- fp32 -> fp16 pre-pass (each value rounded exactly once) ---
    cvt_kernel<<<16384, 256>>>(hidden, h_h);
    cvt_kernel<<<512,   256>>>(aux,    a_h);
    cvt_kernel<<<128,   256>>>(wq1, wq1h);
    cvt_kernel<<<256,   256>>>(wk1, wk1h);
    cvt_kernel<<<512,   256>>>(wv1, wv1h);
    cvt_kernel<<<256,   256>>>(wo1, wo1h);
    cvt_kernel<<<256,   256>>>(wq2, wq2h);
    cvt_kernel<<<128,   256>>>(wk2, wk2h);
    cvt_kernel<<<256,   256>>>(wv2, wv2h);
    cvt_kernel<<<512,   256>>>(wo2, wo2h);

    // --- projections (fp16 in, fp16 out) ---
    hgemm_t<<<dim3(4, 16), 256, HT_SMEM>>>(a_h, wq1h, bq1, nullptr, q1h,
        512, 512, 512, 512, 0, 0, 0, 0, 0, 0, 1, 1.f);
    hgemm_t<<<dim3(4, 256), 256, HT_SMEM>>>(h_h, wk1h, bk1, nullptr, k1h,
        1024, 1024, 1024, 512, 0, 0, 0, 0, 0, 0, 1, 1.f);
    hgemm_t<<<dim3(8, 256), 256, HT_SMEM>>>(h_h, wv1h, bv1, nullptr, v1h,
        1024, 1024, 1024, 1024, 0, 0, 0, 0, 0, 0, 1, 1.f);
    hgemm_t<<<dim3(4, 256), 256, HT_SMEM>>>(h_h, wq2h, bq2, nullptr, q2h,
        1024, 1024, 1024, 512, 0, 0, 0, 0, 0, 0, 1, 1.f);

    // --- pack attention: scores (b,h): 256 x 4096, headdim 64 ---
    hgemm_t<<<dim3(32, 2, 64), 256, HT_SMEM>>>(q1h, k1h, nullptr, attn1, nullptr,
        64, 512, 512, 4096,
        (long long)K_ * QK_, 64,
        (long long)HW_ * QK_, 64,
        (long long)NH_ * K_ * HW_, (long long)K_ * HW_, NH_, SCALE_);
    softmax4096_kernel<<<16384, 256>>>(attn1, attn1h);
    hgemm_nn<<<dim3(1, 2, 64), 256, HN_SMEM>>>(attn1h, v1h, nullptr, ao1h,
        4096, 4096, 1024, 1024,
        (long long)NH_ * K_ * HW_, (long long)K_ * HW_,
        (long long)HW_ * HID_, HD_,
        (long long)K_ * HID_, HD_, NH_);
    hgemm_t<<<dim3(4, 16), 256, HT_SMEM>>>(ao1h, wo1h, bo1, out1f, out1h,
        1024, 1024, 1024, 512, 0, 0, 0, 0, 0, 0, 1, 1.f);
    add_ln_kernel<2><<<2048, 256>>>(aux, out1f, g_aux, b_aux, aux_out, 512);

    // --- unpack attention ---
    hgemm_t<<<dim3(4, 16), 256, HT_SMEM>>>(out1h, wk2h, bk2, nullptr, k2h,
        512, 512, 512, 512, 0, 0, 0, 0, 0, 0, 1, 1.f);
    hgemm_t<<<dim3(8, 16), 256, HT_SMEM>>>(out1h, wv2h, bv2, nullptr, v2h,
        512, 512, 512, 1024, 0, 0, 0, 0, 0, 0, 1, 1.f);
    hgemm_t<<<dim3(2, 32, 64), 256, HT_SMEM>>>(q2h, k2h, nullptr, attn2, nullptr,
        64, 512, 512, 256,
        (long long)HW_ * QK_, 64,
        (long long)K_ * QK_, 64,
        (long long)NH_ * HW_ * K_, (long long)HW_ * K_, NH_, SCALE_);
    softmax256_kernel<<<32768, 256>>>(attn2, attn2h);
    hgemm_nn<<<dim3(1, 32, 64), 256, HN_SMEM>>>(attn2h, v2h, nullptr, ao2h,
        256, 256, 1024, 1024,
        (long long)NH_ * HW_ * K_, (long long)HW_ * K_,
        (long long)K_ * HID_, HD_,
        (long long)HW_ * HID_, HD_, NH_);
    hgemm_t<<<dim3(8, 256), 256, HT_SMEM>>>(ao2h, wo2h, bo2, out2p, nullptr,
        1024, 1024, 1024, 1024, 0, 0, 0, 0, 0, 0, 1, 1.f);
    add_ln_kernel<4><<<32768, 256>>>(hidden, out2p, g_h, b_h, out, 1024);
}

// round 9
// speedup vs baseline: 1.8990x; 1.0834x over previous
#include <cuda_runtime.h>
#include <cuda_fp16.h>
#include <math.h>
#include <stdint.h>

#define B_    8
#define HW_   4096
#define K_    256
#define HID_  1024
#define AUX_  512
#define QK_   512
#define NH_   8
#define HD_   128
#define SCALE_ 0.08838834764831845f   // 1/sqrt(128)

// scratch: fp32 region then fp16 region (see offsets in kernel_launch)
__device__ float g_scratch[175374336];

// ---------------- helpers -----------------------------------------------------
__device__ __forceinline__ void cp16(void* s, const void* g) {
    uint32_t sa = (uint32_t)__cvta_generic_to_shared(s);
    asm volatile("cp.async.cg.shared.global [%0], [%1], 16;" :: "r"(sa), "l"(g));
}
__device__ __forceinline__ void ldsm4(uint32_t* r, uint32_t a) {
    asm volatile("ldmatrix.sync.aligned.m8n8.x4.shared.b16 {%0,%1,%2,%3}, [%4];"
        : "=r"(r[0]), "=r"(r[1]), "=r"(r[2]), "=r"(r[3]) : "r"(a));
}
__device__ __forceinline__ void ldsm4t(uint32_t* r, uint32_t a) {
    asm volatile("ldmatrix.sync.aligned.m8n8.x4.trans.shared.b16 {%0,%1,%2,%3}, [%4];"
        : "=r"(r[0]), "=r"(r[1]), "=r"(r[2]), "=r"(r[3]) : "r"(a));
}
__device__ __forceinline__ void mma16(float* c, const uint32_t* a, const uint32_t* b) {
    asm volatile(
        "mma.sync.aligned.m16n8k16.row.col.f32.f16.f16.f32 "
        "{%0,%1,%2,%3}, {%4,%5,%6,%7}, {%8,%9}, {%0,%1,%2,%3};"
        : "+f"(c[0]), "+f"(c[1]), "+f"(c[2]), "+f"(c[3])
        : "r"(a[0]), "r"(a[1]), "r"(a[2]), "r"(a[3]), "r"(b[0]), "r"(b[1]));
}

// ---------------- fp32 -> fp16 conversion pre-pass ----------------------------
__global__ __launch_bounds__(256) void cvt_kernel(const float* __restrict__ x,
                                                  __half* __restrict__ y)
{
    const size_t i = ((size_t)blockIdx.x * 256 + threadIdx.x) * 8;
    float4 a = *reinterpret_cast<const float4*>(x + i);
    float4 b = *reinterpret_cast<const float4*>(x + i + 4);
    __half2 h0 = __floats2half2_rn(a.x, a.y);
    __half2 h1 = __floats2half2_rn(a.z, a.w);
    __half2 h2 = __floats2half2_rn(b.x, b.y);
    __half2 h3 = __floats2half2_rn(b.z, b.w);
    uint4 o;
    o.x = *reinterpret_cast<uint32_t*>(&h0);
    o.y = *reinterpret_cast<uint32_t*>(&h1);
    o.z = *reinterpret_cast<uint32_t*>(&h2);
    o.w = *reinterpret_cast<uint32_t*>(&h3);
    *reinterpret_cast<uint4*>(y + i) = o;
}

// ======== fp16 TRANSB GEMM: C[M,N] = alpha*A[M,K]*B[N,K]^T + bias =============
// Tile 128x128, BK=64, 2-stage cp.async, 8 warps 64x32, ldmatrix + m16n8k16.
#define HT_SA   72                    // halfs per smem row (64 + 8 pad)
#define HT_STG  (128 * HT_SA)         // halfs per operand stage
#define HT_PAIR (2 * HT_STG)
#define HT_SMEM (2 * HT_PAIR * 2)     // 73728 bytes

__global__ __launch_bounds__(256, 2) void hgemm_t(
    const __half* __restrict__ A, const __half* __restrict__ Bm,
    const float* __restrict__ bias, float* __restrict__ Cf, __half* __restrict__ Ch,
    int Kd, int lda, int ldb, int ldc,
    long long sAb, long long sAh, long long sBb, long long sBh,
    long long sCb, long long sCh, int nh, float alpha)
{
    extern __shared__ __half hsm[];
    const int z = blockIdx.z, bb = z / nh, hh = z - bb * nh;
    A  += bb * sAb + hh * sAh;
    Bm += bb * sBb + hh * sBh;
    const long long cO = bb * sCb + hh * sCh;

    const int m0 = blockIdx.y * 128, n0 = blockIdx.x * 128;
    const int t = threadIdx.x, lane = t & 31, warp = t >> 5;
    const int wm = (warp >> 2) * 64, wn = (warp & 3) * 32;
    const uint32_t smb = (uint32_t)__cvta_generic_to_shared(hsm);

    float acc[4][4][4];
#pragma unroll
    for (int i = 0; i < 4; i++)
#pragma unroll
        for (int j = 0; j < 4; j++)
#pragma unroll
            for (int r = 0; r < 4; r++) acc[i][j][r] = 0.f;

    auto fill = [&](int s, int ck) {
        __half* Sa = hsm + s * HT_PAIR;
        __half* Sb = Sa + HT_STG;
        const int k0 = ck * 64;
#pragma unroll
        for (int i = 0; i < 4; i++) {   // 128 rows x 8 16B-chunks = 1024 chunks
            int c = t + i * 256, row = c >> 3, o = (c & 7) * 8;
            cp16(&Sa[row * HT_SA + o], A + (size_t)(m0 + row) * lda + k0 + o);
        }
#pragma unroll
        for (int i = 0; i < 4; i++) {
            int c = t + i * 256, row = c >> 3, o = (c & 7) * 8;
            cp16(&Sb[row * HT_SA + o], Bm + (size_t)(n0 + row) * ldb + k0 + o);
        }
    };

    const int nchunk = Kd >> 6;        // BK = 64
    fill(0, 0);
    asm volatile("cp.async.commit_group;");
    if (nchunk > 1) fill(1, 1);
    asm volatile("cp.async.commit_group;");

    const int lrow = lane & 15;
    const int lcol = (lane >> 4) * 8;

    for (int ck = 0; ck < nchunk; ck++) {
        if (ck + 1 >= nchunk) asm volatile("cp.async.wait_group 0;");
        else                  asm volatile("cp.async.wait_group 1;");
        __syncthreads();

        const uint32_t sA = smb + (uint32_t)((ck & 1) * HT_PAIR) * 2;
        const uint32_t sB = sA + HT_STG * 2;
#pragma unroll
        for (int ks = 0; ks < 4; ks++) {
            uint32_t af[4][4], bq[2][4];
#pragma unroll
            for (int mt = 0; mt < 4; mt++)
                ldsm4(af[mt], sA + 2 * ((wm + mt * 16 + lrow) * HT_SA + ks * 16 + lcol));
#pragma unroll
            for (int p = 0; p < 2; p++)
                ldsm4(bq[p], sB + 2 * ((wn + p * 16 + lrow) * HT_SA + ks * 16 + lcol));
#pragma unroll
            for (int mt = 0; mt < 4; mt++)
#pragma unroll
                for (int p = 0; p < 2; p++) {
                    uint32_t b0[2] = { bq[p][0], bq[p][2] };
                    uint32_t b1[2] = { bq[p][1], bq[p][3] };
                    mma16(acc[mt][2 * p],     af[mt], b0);
                    mma16(acc[mt][2 * p + 1], af[mt], b1);
                }
        }
        __syncthreads();
        if (ck + 2 < nchunk) fill(ck & 1, ck + 2);
        asm volatile("cp.async.commit_group;");
    }

    const int gid = lane >> 2, tig = lane & 3;
#pragma unroll
    for (int mt = 0; mt < 4; mt++) {
        const int row = m0 + wm + mt * 16 + gid;
#pragma unroll
        for (int nt = 0; nt < 4; nt++) {
            const int col = n0 + wn + nt * 8 + tig * 2;
            float b0v = 0.f, b1v = 0.f;
            if (bias) { b0v = bias[col]; b1v = bias[col + 1]; }
#pragma unroll
            for (int h = 0; h < 2; h++) {
                float2 v;
                v.x = acc[mt][nt][h * 2 + 0] * alpha + b0v;
                v.y = acc[mt][nt][h * 2 + 1] * alpha + b1v;
                const long long idx = cO + (long long)(row + h * 8) * ldc + col;
                if (Cf) *reinterpret_cast<float2*>(Cf + idx) = v;
                if (Ch) {
                    __half2 hv = __floats2half2_rn(v.x, v.y);
                    *reinterpret_cast<__half2*>(Ch + idx) = hv;
                }
            }
        }
    }
}

// ======== fp16 NN GEMM (attn @ V): A[M,K] k-contig, B[K,N] n-contig ===========
#define HN_SB   136
#define HN_BSTG (64 * HN_SB)
#define HN_PAIR (HT_STG + HN_BSTG)
#define HN_SMEM (2 * HN_PAIR * 2)     // 71680 bytes

__global__ __launch_bounds__(256, 2) void hgemm_nn(
    const __half* __restrict__ A, const __half* __restrict__ Bm,
    float* __restrict__ Cf, __half* __restrict__ Ch,
    int Kd, int lda, int ldb, int ldc,
    long long sAb, long long sAh, long long sBb, long long sBh,
    long long sCb, long long sCh, int nh)
{
    extern __shared__ __half hsm[];
    const int z = blockIdx.z, bb = z / nh, hh = z - bb * nh;
    A  += bb * sAb + hh * sAh;
    Bm += bb * sBb + hh * sBh;
    const long long cO = bb * sCb + hh * sCh;

    const int m0 = blockIdx.y * 128, n0 = blockIdx.x * 128;
    const int t = threadIdx.x, lane = t & 31, warp = t >> 5;
    const int wm = (warp >> 2) * 64, wn = (warp & 3) * 32;
    const uint32_t smb = (uint32_t)__cvta_generic_to_shared(hsm);

    float acc[4][4][4];
#pragma unroll
    for (int i = 0; i < 4; i++)
#pragma unroll
        for (int j = 0; j < 4; j++)
#pragma unroll
            for (int r = 0; r < 4; r++) acc[i][j][r] = 0.f;

    auto fill = [&](int s, int ck) {
        __half* Sa = hsm + s * HN_PAIR;
        __half* Sb = Sa + HT_STG;
        const int k0 = ck * 64;
#pragma unroll
        for (int i = 0; i < 4; i++) {
            int c = t + i * 256, row = c >> 3, o = (c & 7) * 8;
            cp16(&Sa[row * HT_SA + o], A + (size_t)(m0 + row) * lda + k0 + o);
        }
#pragma unroll
        for (int i = 0; i < 4; i++) {   // 64 rows x 16 chunks = 1024 chunks
            int c = t + i * 256, row = c >> 4, o = (c & 15) * 8;
            cp16(&Sb[row * HN_SB + o], Bm + (size_t)(k0 + row) * ldb + n0 + o);
        }
    };

    const int nchunk = Kd >> 6;
    fill(0, 0);
    asm volatile("cp.async.commit_group;");
    if (nchunk > 1) fill(1, 1);
    asm volatile("cp.async.commit_group;");

    const int lrow  = lane & 15;
    const int lcol  = (lane >> 4) * 8;
    const int tkrow = ((lane >> 3) & 1) * 8 + (lane & 7);
    const int tncol = (lane >> 4) * 8;

    for (int ck = 0; ck < nchunk; ck++) {
        if (ck + 1 >= nchunk) asm volatile("cp.async.wait_group 0;");
        else                  asm volatile("cp.async.wait_group 1;");
        __syncthreads();

        const uint32_t sA = smb + (uint32_t)((ck & 1) * HN_PAIR) * 2;
        const uint32_t sB = sA + HT_STG * 2;
#pragma unroll
        for (int ks = 0; ks < 4; ks++) {
            uint32_t af[4][4], bq[2][4];
#pragma unroll
            for (int mt = 0; mt < 4; mt++)
                ldsm4(af[mt], sA + 2 * ((wm + mt * 16 + lrow) * HT_SA + ks * 16 + lcol));
#pragma unroll
            for (int p = 0; p < 2; p++)
                ldsm4t(bq[p], sB + 2 * ((ks * 16 + tkrow) * HN_SB + wn + p * 16 + tncol));
#pragma unroll
            for (int mt = 0; mt < 4; mt++)
#pragma unroll
                for (int p = 0; p < 2; p++) {
                    uint32_t b0[2] = { bq[p][0], bq[p][1] };
                    uint32_t b1[2] = { bq[p][2], bq[p][3] };
                    mma16(acc[mt][2 * p],     af[mt], b0);
                    mma16(acc[mt][2 * p + 1], af[mt], b1);
                }
        }
        __syncthreads();
        if (ck + 2 < nchunk) fill(ck & 1, ck + 2);
        asm volatile("cp.async.commit_group;");
    }

    const int gid = lane >> 2, tig = lane & 3;
#pragma unroll
    for (int mt = 0; mt < 4; mt++) {
        const int row = m0 + wm + mt * 16 + gid;
#pragma unroll
        for (int nt = 0; nt < 4; nt++) {
            const int col = n0 + wn + nt * 8 + tig * 2;
#pragma unroll
            for (int h = 0; h < 2; h++) {
                float2 v;
                v.x = acc[mt][nt][h * 2 + 0];
                v.y = acc[mt][nt][h * 2 + 1];
                const long long idx = cO + (long long)(row + h * 8) * ldc + col;
                if (Cf) *reinterpret_cast<float2*>(Cf + idx) = v;
                if (Ch) {
                    __half2 hv = __floats2half2_rn(v.x, v.y);
                    *reinterpret_cast<__half2*>(Ch + idx) = hv;
                }
            }
        }
    }
}

// ---------------- softmax, L = 4096 (fp32 in-place + fp16 copy) ---------------
__global__ __launch_bounds__(256) void softmax4096_kernel(float* __restrict__ X,
                                                          __half* __restrict__ Xh)
{
    float* x = X + (size_t)blockIdx.x * 4096;
    __half* xh = Xh + (size_t)blockIdx.x * 4096;
    const int t = threadIdx.x;
    float v[16];
    float m = -1e30f;
#pragma unroll
    for (int i = 0; i < 16; i++) { v[i] = x[t + i * 256]; m = fmaxf(m, v[i]); }
    __shared__ float red[8];
    const int lane = t & 31, w = t >> 5;
#pragma unroll
    for (int o = 16; o > 0; o >>= 1) m = fmaxf(m, __shfl_xor_sync(0xffffffffu, m, o));
    if (lane == 0) red[w] = m;
    __syncthreads();
    float bm = red[0];
#pragma unroll
    for (int i = 1; i < 8; i++) bm = fmaxf(bm, red[i]);
    float s = 0.f;
#pragma unroll
    for (int i = 0; i < 16; i++) { v[i] = __expf(v[i] - bm); s += v[i]; }
#pragma unroll
    for (int o = 16; o > 0; o >>= 1) s += __shfl_xor_sync(0xffffffffu, s, o);
    __syncthreads();
    if (lane == 0) red[w] = s;
    __syncthreads();
    float bs = 0.f;
#pragma unroll
    for (int i = 0; i < 8; i++) bs += red[i];
    const float inv = 1.0f / bs;
#pragma unroll
    for (int i = 0; i < 16; i++) {
        float r = v[i] * inv;
        x[t + i * 256]  = r;
        xh[t + i * 256] = __float2half_rn(r);
    }
}

// ---------------- softmax, L = 256 --------------------------------------------
__global__ __launch_bounds__(256) void softmax256_kernel(float* __restrict__ X,
                                                         __half* __restrict__ Xh)
{
    const int lane = threadIdx.x & 31;
    const int w    = threadIdx.x >> 5;
    const size_t rb = ((size_t)blockIdx.x * 8 + w) * 256;
    float* x = X + rb;
    __half* xh = Xh + rb;
    float v[8];
    float m = -1e30f;
#pragma unroll
    for (int i = 0; i < 8; i++) { v[i] = x[lane + i * 32]; m = fmaxf(m, v[i]); }
#pragma unroll
    for (int o = 16; o > 0; o >>= 1) m = fmaxf(m, __shfl_xor_sync(0xffffffffu, m, o));
    float s = 0.f;
#pragma unroll
    for (int i = 0; i < 8; i++) { v[i] = __expf(v[i] - m); s += v[i]; }
#pragma unroll
    for (int o = 16; o > 0; o >>= 1) s += __shfl_xor_sync(0xffffffffu, s, o);
    const float inv = 1.0f / s;
#pragma unroll
    for (int i = 0; i < 8; i++) {
        float r = v[i] * inv;
        x[lane + i * 32]  = r;
        xh[lane + i * 32] = __float2half_rn(r);
    }
}

// ---------------- residual add + LayerNorm ------------------------------------
template<int VPT>
__global__ __launch_bounds__(256) void add_ln_kernel(
    const float* __restrict__ R, const float* __restrict__ X,
    const float* __restrict__ g, const float* __restrict__ bta,
    float* __restrict__ Y, int D)
{
    const size_t row = blockIdx.x;
    const float* r = R + row * D;
    const float* x = X + row * D;
    float* y = Y + row * D;
    const int t = threadIdx.x;
    float v[VPT];
    float s = 0.f, sq = 0.f;
#pragma unroll
    for (int i = 0; i < VPT; i++) {
        const int c = t + i * 256;
        v[i] = r[c] + x[c];
        s += v[i]; sq += v[i] * v[i];
    }
    const int lane = t & 31, w = t >> 5;
#pragma unroll
    for (int o = 16; o > 0; o >>= 1) {
        s  += __shfl_xor_sync(0xffffffffu, s, o);
        sq += __shfl_xor_sync(0xffffffffu, sq, o);
    }
    __shared__ float rs[8], rq[8];
    if (lane == 0) { rs[w] = s; rq[w] = sq; }
    __syncthreads();
    s = 0.f; sq = 0.f;
#pragma unroll
    for (int i = 0; i < 8; i++) { s += rs[i]; sq += rq[i]; }
    const float mean = s / D;
    const float var  = sq / D - mean * mean;
    const float inv  = rsqrtf(var + 1e-5f);
#pragma unroll
    for (int i = 0; i < VPT; i++) {
        const int c = t + i * 256;
        y[c] = (v[i] - mean) * inv * g[c] + bta[c];
    }
}

// ---------------- launch --------------------------------------------------------
extern "C" void kernel_launch(void* const* d_in, const int* in_sizes, int n_in,
                              void* d_out, int out_size)
{
    const float* hidden = (const float*)d_in[0];
    const float* aux    = (const float*)d_in[1];
    const float* wq1 = (const float*)d_in[2];  const float* bq1 = (const float*)d_in[3];
    const float* wk1 = (const float*)d_in[4];  const float* bk1 = (const float*)d_in[5];
    const float* wv1 = (const float*)d_in[6];  const float* bv1 = (const float*)d_in[7];
    const float* wo1 = (const float*)d_in[8];  const float* bo1 = (const float*)d_in[9];
    const float* wq2 = (const float*)d_in[10]; const float* bq2 = (const float*)d_in[11];
    const float* wk2 = (const float*)d_in[12]; const float* bk2 = (const float*)d_in[13];
    const float* wv2 = (const float*)d_in[14]; const float* bv2 = (const float*)d_in[15];
    const float* wo2 = (const float*)d_in[16]; const float* bo2 = (const float*)d_in[17];
    const float* g_aux = (const float*)d_in[18]; const float* b_aux = (const float*)d_in[19];
    const float* g_h   = (const float*)d_in[20]; const float* b_h   = (const float*)d_in[21];

    cudaFuncSetAttribute(hgemm_t,
        cudaFuncAttributeMaxDynamicSharedMemorySize, HT_SMEM);
    cudaFuncSetAttribute(hgemm_nn,
        cudaFuncAttributeMaxDynamicSharedMemorySize, HN_SMEM);

    float* scratch = nullptr;
    cudaGetSymbolAddress((void**)&scratch, g_scratch);

    // fp32 region
    float* out2p = scratch;                 // 33,554,432
    float* out1f = scratch + 33554432;      // 1,048,576
    // fp16 region
    __half* hb = (__half*)(scratch + 34603008);
    __half* h_h    = hb;
    __half* a_h    = hb + 33554432;
    __half* wq1h   = hb + 34603008;
    __half* wk1h   = hb + 34865152;
    __half* wv1h   = hb + 35389440;
    __half* wo1h   = hb + 36438016;
    __half* wq2h   = hb + 36962304;
    __half* wk2h   = hb + 37486592;
    __half* wv2h   = hb + 37748736;
    __half* wo2h   = hb + 38273024;
    __half* q1h    = hb + 39321600;
    __half* k1h    = hb + 40370176;
    __half* v1h    = hb + 57147392;
    __half* q2h    = hb + 90701824;
    __half* k2h    = hb + 107479040;
    __half* v2h    = hb + 108527616;
    __half* ao1h   = hb + 110624768;
    __half* ao2h   = hb + 112721920;
    __half* out1h  = hb + 146276352;
    __half* attn1h = hb + 147324928;
    __half* attn2h = hb + 214433792;

    float* out     = (float*)d_out;
    float* aux_out = out + (size_t)B_ * HW_ * HID_;
    float* attn2   = aux_out + (size_t)B_ * K_ * AUX_;
    float* attn1   = attn2 + (size_t)B_ * NH_ * HW_ * K_;

    // --- fp32 -> fp16 pre-pass (each value rounded exactly once) ---
    cvt_kernel<<<16384, 256>>>(hidden, h_h);
    cvt_kernel<<<512,   256>>>(aux,    a_h);
    cvt_kernel<<<128,   256>>>(wq1, wq1h);
    cvt_kernel<<<256,   256>>>(wk1, wk1h);
    cvt_kernel<<<512,   256>>>(wv1, wv1h);
    cvt_kernel<<<256,   256>>>(wo1, wo1h);
    cvt_kernel<<<256,   256>>>(wq2, wq2h);
    cvt_kernel<<<128,   256>>>(wk2, wk2h);
    cvt_kernel<<<256,   256>>>(wv2, wv2h);
    cvt_kernel<<<512,   256>>>(wo2, wo2h);

    // --- projections (fp16 in, fp16 out) ---
    hgemm_t<<<dim3(4, 16), 256, HT_SMEM>>>(a_h, wq1h, bq1, nullptr, q1h,
        512, 512, 512, 512, 0, 0, 0, 0, 0, 0, 1, 1.f);
    hgemm_t<<<dim3(4, 256), 256, HT_SMEM>>>(h_h, wk1h, bk1, nullptr, k1h,
        1024, 1024, 1024, 512, 0, 0, 0, 0, 0, 0, 1, 1.f);
    hgemm_t<<<dim3(8, 256), 256, HT_SMEM>>>(h_h, wv1h, bv1, nullptr, v1h,
        1024, 1024, 1024, 1024, 0, 0, 0, 0, 0, 0, 1, 1.f);
    hgemm_t<<<dim3(4, 256), 256, HT_SMEM>>>(h_h, wq2h, bq2, nullptr, q2h,
        1024, 1024, 1024, 512, 0, 0, 0, 0, 0, 0, 1, 1.f);

    // --- pack attention: scores (b,h): 256 x 4096, headdim 64 ---
    hgemm_t<<<dim3(32, 2, 64), 256, HT_SMEM>>>(q1h, k1h, nullptr, attn1, nullptr,
        64, 512, 512, 4096,
        (long long)K_ * QK_, 64,
        (long long)HW_ * QK_, 64,
        (long long)NH_ * K_ * HW_, (long long)K_ * HW_, NH_, SCALE_);
    softmax4096_kernel<<<16384, 256>>>(attn1, attn1h);
    hgemm_nn<<<dim3(1, 2, 64), 256, HN_SMEM>>>(attn1h, v1h, nullptr, ao1h,
        4096, 4096, 1024, 1024,
        (long long)NH_ * K_ * HW_, (long long)K_ * HW_,
        (long long)HW_ * HID_, HD_,
        (long long)K_ * HID_, HD_, NH_);
    hgemm_t<<<dim3(4, 16), 256, HT_SMEM>>>(ao1h, wo1h, bo1, out1f, out1h,
        1024, 1024, 1024, 512, 0, 0, 0, 0, 0, 0, 1, 1.f);
    add_ln_kernel<2><<<2048, 256>>>(aux, out1f, g_aux, b_aux, aux_out, 512);

    // --- unpack attention ---
    hgemm_t<<<dim3(4, 16), 256, HT_SMEM>>>(out1h, wk2h, bk2, nullptr, k2h,
        512, 512, 512, 512, 0, 0, 0, 0, 0, 0, 1, 1.f);
    hgemm_t<<<dim3(8, 16), 256, HT_SMEM>>>(out1h, wv2h, bv2, nullptr, v2h,
        512, 512, 512, 1024, 0, 0, 0, 0, 0, 0, 1, 1.f);
    hgemm_t<<<dim3(2, 32, 64), 256, HT_SMEM>>>(q2h, k2h, nullptr, attn2, nullptr,
        64, 512, 512, 256,
        (long long)HW_ * QK_, 64,
        (long long)K_ * QK_, 64,
        (long long)NH_ * HW_ * K_, (long long)HW_ * K_, NH_, SCALE_);
    softmax256_kernel<<<32768, 256>>>(attn2, attn2h);
    hgemm_nn<<<dim3(1, 32, 64), 256, HN_SMEM>>>(attn2h, v2h, nullptr, ao2h,
        256, 256, 1024, 1024,
        (long long)NH_ * HW_ * K_, (long long)HW_ * K_,
        (long long)K_ * HID_, HD_,
        (long long)HW_ * HID_, HD_, NH_);
    hgemm_t<<<dim3(8, 256), 256, HT_SMEM>>>(ao2h, wo2h, bo2, out2p, nullptr,
        1024, 1024, 1024, 1024, 0, 0, 0, 0, 0, 0, 1, 1.f);
    add_ln_kernel<4><<<32768, 256>>>(hidden, out2p, g_h, b_h, out, 1024);
}

// round 10
// speedup vs baseline: 1.9383x; 1.0207x over previous
#include <cuda_runtime.h>
#include <cuda_fp16.h>
#include <math.h>
#include <stdint.h>

#define B_    8
#define HW_   4096
#define K_    256
#define HID_  1024
#define AUX_  512
#define QK_   512
#define NH_   8
#define HD_   128
#define SCALE_ 0.08838834764831845f   // 1/sqrt(128)

// scratch: fp32 region (out2p, out1f, bias concats) then fp16 region
__device__ float g_scratch[175377920];

// ---------------- helpers -----------------------------------------------------
__device__ __forceinline__ void cp16(void* s, const void* g) {
    uint32_t sa = (uint32_t)__cvta_generic_to_shared(s);
    asm volatile("cp.async.cg.shared.global [%0], [%1], 16;" :: "r"(sa), "l"(g));
}
__device__ __forceinline__ void ldsm4(uint32_t* r, uint32_t a) {
    asm volatile("ldmatrix.sync.aligned.m8n8.x4.shared.b16 {%0,%1,%2,%3}, [%4];"
        : "=r"(r[0]), "=r"(r[1]), "=r"(r[2]), "=r"(r[3]) : "r"(a));
}
__device__ __forceinline__ void ldsm4t(uint32_t* r, uint32_t a) {
    asm volatile("ldmatrix.sync.aligned.m8n8.x4.trans.shared.b16 {%0,%1,%2,%3}, [%4];"
        : "=r"(r[0]), "=r"(r[1]), "=r"(r[2]), "=r"(r[3]) : "r"(a));
}
__device__ __forceinline__ void mma16(float* c, const uint32_t* a, const uint32_t* b) {
    asm volatile(
        "mma.sync.aligned.m16n8k16.row.col.f32.f16.f16.f32 "
        "{%0,%1,%2,%3}, {%4,%5,%6,%7}, {%8,%9}, {%0,%1,%2,%3};"
        : "+f"(c[0]), "+f"(c[1]), "+f"(c[2]), "+f"(c[3])
        : "r"(a[0]), "r"(a[1]), "r"(a[2]), "r"(a[3]), "r"(b[0]), "r"(b[1]));
}
__device__ __forceinline__ void cvt8(const float* s, __half* d) {
    float4 a = *reinterpret_cast<const float4*>(s);
    float4 b = *reinterpret_cast<const float4*>(s + 4);
    __half2 h0 = __floats2half2_rn(a.x, a.y);
    __half2 h1 = __floats2half2_rn(a.z, a.w);
    __half2 h2 = __floats2half2_rn(b.x, b.y);
    __half2 h3 = __floats2half2_rn(b.z, b.w);
    uint4 o;
    o.x = *reinterpret_cast<uint32_t*>(&h0);
    o.y = *reinterpret_cast<uint32_t*>(&h1);
    o.z = *reinterpret_cast<uint32_t*>(&h2);
    o.w = *reinterpret_cast<uint32_t*>(&h3);
    *reinterpret_cast<uint4*>(d) = o;
}

// ---------------- fp32 -> fp16 conversion -------------------------------------
__global__ __launch_bounds__(256) void cvt_kernel(const float* __restrict__ x,
                                                  __half* __restrict__ y)
{
    const size_t i = ((size_t)blockIdx.x * 256 + threadIdx.x) * 8;
    cvt8(x + i, y + i);
}

// fp16-region half offsets (from hb)
#define OFF_WK1   34603008LL
#define OFF_WV1   35127296LL
#define OFF_WQ2   36175872LL
#define OFF_WQ1   36700160LL
#define OFF_WO1   36962304LL
#define OFF_WK2   37486592LL
#define OFF_WV2   37748736LL
#define OFF_WO2   38273024LL

// all 8 weight matrices in one kernel; [wk1|wv1|wq2] and [wk2|wv2] contiguous
__global__ __launch_bounds__(256) void cvt_weights(
    const float* __restrict__ wk1, const float* __restrict__ wv1,
    const float* __restrict__ wq2, const float* __restrict__ wq1,
    const float* __restrict__ wo1, const float* __restrict__ wk2,
    const float* __restrict__ wv2, const float* __restrict__ wo2,
    __half* __restrict__ hb)
{
    const int g = blockIdx.x * 256 + threadIdx.x;   // one 8-elem chunk per thread
    const float* s; long long d;
    if      (g < 65536)  { s = wk1 + (size_t)g * 8;            d = OFF_WK1 + (long long)g * 8; }
    else if (g < 196608) { s = wv1 + (size_t)(g - 65536)  * 8; d = OFF_WV1 + (long long)(g - 65536)  * 8; }
    else if (g < 262144) { s = wq2 + (size_t)(g - 196608) * 8; d = OFF_WQ2 + (long long)(g - 196608) * 8; }
    else if (g < 294912) { s = wq1 + (size_t)(g - 262144) * 8; d = OFF_WQ1 + (long long)(g - 262144) * 8; }
    else if (g < 360448) { s = wo1 + (size_t)(g - 294912) * 8; d = OFF_WO1 + (long long)(g - 294912) * 8; }
    else if (g < 393216) { s = wk2 + (size_t)(g - 360448) * 8; d = OFF_WK2 + (long long)(g - 360448) * 8; }
    else if (g < 458752) { s = wv2 + (size_t)(g - 393216) * 8; d = OFF_WV2 + (long long)(g - 393216) * 8; }
    else                 { s = wo2 + (size_t)(g - 458752) * 8; d = OFF_WO2 + (long long)(g - 458752) * 8; }
    cvt8(s, hb + d);
}

// ======== fp16 TRANSB GEMM: C[M,N] = alpha*A[M,K]*B[N,K]^T + bias =============
#define HT_SA   72
#define HT_STG  (128 * HT_SA)
#define HT_PAIR (2 * HT_STG)
#define HT_SMEM (2 * HT_PAIR * 2)     // 73728 bytes

__global__ __launch_bounds__(256, 2) void hgemm_t(
    const __half* __restrict__ A, const __half* __restrict__ Bm,
    const float* __restrict__ bias, float* __restrict__ Cf, __half* __restrict__ Ch,
    int Kd, int lda, int ldb, int ldc,
    long long sAb, long long sAh, long long sBb, long long sBh,
    long long sCb, long long sCh, int nh, float alpha)
{
    extern __shared__ __half hsm[];
    const int z = blockIdx.z, bb = z / nh, hh = z - bb * nh;
    A  += bb * sAb + hh * sAh;
    Bm += bb * sBb + hh * sBh;
    const long long cO = bb * sCb + hh * sCh;

    const int m0 = blockIdx.y * 128, n0 = blockIdx.x * 128;
    const int t = threadIdx.x, lane = t & 31, warp = t >> 5;
    const int wm = (warp >> 2) * 64, wn = (warp & 3) * 32;
    const uint32_t smb = (uint32_t)__cvta_generic_to_shared(hsm);

    float acc[4][4][4];
#pragma unroll
    for (int i = 0; i < 4; i++)
#pragma unroll
        for (int j = 0; j < 4; j++)
#pragma unroll
            for (int r = 0; r < 4; r++) acc[i][j][r] = 0.f;

    auto fill = [&](int s, int ck) {
        __half* Sa = hsm + s * HT_PAIR;
        __half* Sb = Sa + HT_STG;
        const int k0 = ck * 64;
#pragma unroll
        for (int i = 0; i < 4; i++) {
            int c = t + i * 256, row = c >> 3, o = (c & 7) * 8;
            cp16(&Sa[row * HT_SA + o], A + (size_t)(m0 + row) * lda + k0 + o);
        }
#pragma unroll
        for (int i = 0; i < 4; i++) {
            int c = t + i * 256, row = c >> 3, o = (c & 7) * 8;
            cp16(&Sb[row * HT_SA + o], Bm + (size_t)(n0 + row) * ldb + k0 + o);
        }
    };

    const int nchunk = Kd >> 6;
    fill(0, 0);
    asm volatile("cp.async.commit_group;");
    if (nchunk > 1) fill(1, 1);
    asm volatile("cp.async.commit_group;");

    const int lrow = lane & 15;
    const int lcol = (lane >> 4) * 8;

    for (int ck = 0; ck < nchunk; ck++) {
        if (ck + 1 >= nchunk) asm volatile("cp.async.wait_group 0;");
        else                  asm volatile("cp.async.wait_group 1;");
        __syncthreads();

        const uint32_t sA = smb + (uint32_t)((ck & 1) * HT_PAIR) * 2;
        const uint32_t sB = sA + HT_STG * 2;
#pragma unroll
        for (int ks = 0; ks < 4; ks++) {
            uint32_t af[4][4], bq[2][4];
#pragma unroll
            for (int mt = 0; mt < 4; mt++)
                ldsm4(af[mt], sA + 2 * ((wm + mt * 16 + lrow) * HT_SA + ks * 16 + lcol));
#pragma unroll
            for (int p = 0; p < 2; p++)
                ldsm4(bq[p], sB + 2 * ((wn + p * 16 + lrow) * HT_SA + ks * 16 + lcol));
#pragma unroll
            for (int mt = 0; mt < 4; mt++)
#pragma unroll
                for (int p = 0; p < 2; p++) {
                    uint32_t b0[2] = { bq[p][0], bq[p][2] };
                    uint32_t b1[2] = { bq[p][1], bq[p][3] };
                    mma16(acc[mt][2 * p],     af[mt], b0);
                    mma16(acc[mt][2 * p + 1], af[mt], b1);
                }
        }
        __syncthreads();
        if (ck + 2 < nchunk) fill(ck & 1, ck + 2);
        asm volatile("cp.async.commit_group;");
    }

    const int gid = lane >> 2, tig = lane & 3;
#pragma unroll
    for (int mt = 0; mt < 4; mt++) {
        const int row = m0 + wm + mt * 16 + gid;
#pragma unroll
        for (int nt = 0; nt < 4; nt++) {
            const int col = n0 + wn + nt * 8 + tig * 2;
            float b0v = 0.f, b1v = 0.f;
            if (bias) { b0v = bias[col]; b1v = bias[col + 1]; }
#pragma unroll
            for (int h = 0; h < 2; h++) {
                float2 v;
                v.x = acc[mt][nt][h * 2 + 0] * alpha + b0v;
                v.y = acc[mt][nt][h * 2 + 1] * alpha + b1v;
                const long long idx = cO + (long long)(row + h * 8) * ldc + col;
                if (Cf) *reinterpret_cast<float2*>(Cf + idx) = v;
                if (Ch) {
                    __half2 hv = __floats2half2_rn(v.x, v.y);
                    *reinterpret_cast<__half2*>(Ch + idx) = hv;
                }
            }
        }
    }
}

// ======== fp16 NN GEMM (attn @ V): A[M,K] k-contig, B[K,N] n-contig ===========
#define HN_SB   136
#define HN_BSTG (64 * HN_SB)
#define HN_PAIR (HT_STG + HN_BSTG)
#define HN_SMEM (2 * HN_PAIR * 2)

__global__ __launch_bounds__(256, 2) void hgemm_nn(
    const __half* __restrict__ A, const __half* __restrict__ Bm,
    float* __restrict__ Cf, __half* __restrict__ Ch,
    int Kd, int lda, int ldb, int ldc,
    long long sAb, long long sAh, long long sBb, long long sBh,
    long long sCb, long long sCh, int nh)
{
    extern __shared__ __half hsm[];
    const int z = blockIdx.z, bb = z / nh, hh = z - bb * nh;
    A  += bb * sAb + hh * sAh;
    Bm += bb * sBb + hh * sBh;
    const long long cO = bb * sCb + hh * sCh;

    const int m0 = blockIdx.y * 128, n0 = blockIdx.x * 128;
    const int t = threadIdx.x, lane = t & 31, warp = t >> 5;
    const int wm = (warp >> 2) * 64, wn = (warp & 3) * 32;
    const uint32_t smb = (uint32_t)__cvta_generic_to_shared(hsm);

    float acc[4][4][4];
#pragma unroll
    for (int i = 0; i < 4; i++)
#pragma unroll
        for (int j = 0; j < 4; j++)
#pragma unroll
            for (int r = 0; r < 4; r++) acc[i][j][r] = 0.f;

    auto fill = [&](int s, int ck) {
        __half* Sa = hsm + s * HN_PAIR;
        __half* Sb = Sa + HT_STG;
        const int k0 = ck * 64;
#pragma unroll
        for (int i = 0; i < 4; i++) {
            int c = t + i * 256, row = c >> 3, o = (c & 7) * 8;
            cp16(&Sa[row * HT_SA + o], A + (size_t)(m0 + row) * lda + k0 + o);
        }
#pragma unroll
        for (int i = 0; i < 4; i++) {
            int c = t + i * 256, row = c >> 4, o = (c & 15) * 8;
            cp16(&Sb[row * HN_SB + o], Bm + (size_t)(k0 + row) * ldb + n0 + o);
        }
    };

    const int nchunk = Kd >> 6;
    fill(0, 0);
    asm volatile("cp.async.commit_group;");
    if (nchunk > 1) fill(1, 1);
    asm volatile("cp.async.commit_group;");

    const int lrow  = lane & 15;
    const int lcol  = (lane >> 4) * 8;
    const int tkrow = ((lane >> 3) & 1) * 8 + (lane & 7);
    const int tncol = (lane >> 4) * 8;

    for (int ck = 0; ck < nchunk; ck++) {
        if (ck + 1 >= nchunk) asm volatile("cp.async.wait_group 0;");
        else                  asm volatile("cp.async.wait_group 1;");
        __syncthreads();

        const uint32_t sA = smb + (uint32_t)((ck & 1) * HN_PAIR) * 2;
        const uint32_t sB = sA + HT_STG * 2;
#pragma unroll
        for (int ks = 0; ks < 4; ks++) {
            uint32_t af[4][4], bq[2][4];
#pragma unroll
            for (int mt = 0; mt < 4; mt++)
                ldsm4(af[mt], sA + 2 * ((wm + mt * 16 + lrow) * HT_SA + ks * 16 + lcol));
#pragma unroll
            for (int p = 0; p < 2; p++)
                ldsm4t(bq[p], sB + 2 * ((ks * 16 + tkrow) * HN_SB + wn + p * 16 + tncol));
#pragma unroll
            for (int mt = 0; mt < 4; mt++)
#pragma unroll
                for (int p = 0; p < 2; p++) {
                    uint32_t b0[2] = { bq[p][0], bq[p][1] };
                    uint32_t b1[2] = { bq[p][2], bq[p][3] };
                    mma16(acc[mt][2 * p],     af[mt], b0);
                    mma16(acc[mt][2 * p + 1], af[mt], b1);
                }
        }
        __syncthreads();
        if (ck + 2 < nchunk) fill(ck & 1, ck + 2);
        asm volatile("cp.async.commit_group;");
    }

    const int gid = lane >> 2, tig = lane & 3;
#pragma unroll
    for (int mt = 0; mt < 4; mt++) {
        const int row = m0 + wm + mt * 16 + gid;
#pragma unroll
        for (int nt = 0; nt < 4; nt++) {
            const int col = n0 + wn + nt * 8 + tig * 2;
#pragma unroll
            for (int h = 0; h < 2; h++) {
                float2 v;
                v.x = acc[mt][nt][h * 2 + 0];
                v.y = acc[mt][nt][h * 2 + 1];
                const long long idx = cO + (long long)(row + h * 8) * ldc + col;
                if (Cf) *reinterpret_cast<float2*>(Cf + idx) = v;
                if (Ch) {
                    __half2 hv = __floats2half2_rn(v.x, v.y);
                    *reinterpret_cast<__half2*>(Ch + idx) = hv;
                }
            }
        }
    }
}

// ---------------- softmax, L = 4096 -------------------------------------------
__global__ __launch_bounds__(256) void softmax4096_kernel(float* __restrict__ X,
                                                          __half* __restrict__ Xh)
{
    float* x = X + (size_t)blockIdx.x * 4096;
    __half* xh = Xh + (size_t)blockIdx.x * 4096;
    const int t = threadIdx.x;
    float v[16];
    float m = -1e30f;
#pragma unroll
    for (int i = 0; i < 16; i++) { v[i] = x[t + i * 256]; m = fmaxf(m, v[i]); }
    __shared__ float red[8];
    const int lane = t & 31, w = t >> 5;
#pragma unroll
    for (int o = 16; o > 0; o >>= 1) m = fmaxf(m, __shfl_xor_sync(0xffffffffu, m, o));
    if (lane == 0) red[w] = m;
    __syncthreads();
    float bm = red[0];
#pragma unroll
    for (int i = 1; i < 8; i++) bm = fmaxf(bm, red[i]);
    float s = 0.f;
#pragma unroll
    for (int i = 0; i < 16; i++) { v[i] = __expf(v[i] - bm); s += v[i]; }
#pragma unroll
    for (int o = 16; o > 0; o >>= 1) s += __shfl_xor_sync(0xffffffffu, s, o);
    __syncthreads();
    if (lane == 0) red[w] = s;
    __syncthreads();
    float bs = 0.f;
#pragma unroll
    for (int i = 0; i < 8; i++) bs += red[i];
    const float inv = 1.0f / bs;
#pragma unroll
    for (int i = 0; i < 16; i++) {
        float r = v[i] * inv;
        x[t + i * 256]  = r;
        xh[t + i * 256] = __float2half_rn(r);
    }
}

// ---------------- softmax, L = 256 --------------------------------------------
__global__ __launch_bounds__(256) void softmax256_kernel(float* __restrict__ X,
                                                         __half* __restrict__ Xh)
{
    const int lane = threadIdx.x & 31;
    const int w    = threadIdx.x >> 5;
    const size_t rb = ((size_t)blockIdx.x * 8 + w) * 256;
    float* x = X + rb;
    __half* xh = Xh + rb;
    float v[8];
    float m = -1e30f;
#pragma unroll
    for (int i = 0; i < 8; i++) { v[i] = x[lane + i * 32]; m = fmaxf(m, v[i]); }
#pragma unroll
    for (int o = 16; o > 0; o >>= 1) m = fmaxf(m, __shfl_xor_sync(0xffffffffu, m, o));
    float s = 0.f;
#pragma unroll
    for (int i = 0; i < 8; i++) { v[i] = __expf(v[i] - m); s += v[i]; }
#pragma unroll
    for (int o = 16; o > 0; o >>= 1) s += __shfl_xor_sync(0xffffffffu, s, o);
    const float inv = 1.0f / s;
#pragma unroll
    for (int i = 0; i < 8; i++) {
        float r = v[i] * inv;
        x[lane + i * 32]  = r;
        xh[lane + i * 32] = __float2half_rn(r);
    }
}

// ---------------- residual add + LayerNorm ------------------------------------
template<int VPT>
__global__ __launch_bounds__(256) void add_ln_kernel(
    const float* __restrict__ R, const float* __restrict__ X,
    const float* __restrict__ g, const float* __restrict__ bta,
    float* __restrict__ Y, int D)
{
    const size_t row = blockIdx.x;
    const float* r = R + row * D;
    const float* x = X + row * D;
    float* y = Y + row * D;
    const int t = threadIdx.x;
    float v[VPT];
    float s = 0.f, sq = 0.f;
#pragma unroll
    for (int i = 0; i < VPT; i++) {
        const int c = t + i * 256;
        v[i] = r[c] + x[c];
        s += v[i]; sq += v[i] * v[i];
    }
    const int lane = t & 31, w = t >> 5;
#pragma unroll
    for (int o = 16; o > 0; o >>= 1) {
        s  += __shfl_xor_sync(0xffffffffu, s, o);
        sq += __shfl_xor_sync(0xffffffffu, sq, o);
    }
    __shared__ float rs[8], rq[8];
    if (lane == 0) { rs[w] = s; rq[w] = sq; }
    __syncthreads();
    s = 0.f; sq = 0.f;
#pragma unroll
    for (int i = 0; i < 8; i++) { s += rs[i]; sq += rq[i]; }
    const float mean = s / D;
    const float var  = sq / D - mean * mean;
    const float inv  = rsqrtf(var + 1e-5f);
#pragma unroll
    for (int i = 0; i < VPT; i++) {
        const int c = t + i * 256;
        y[c] = (v[i] - mean) * inv * g[c] + bta[c];
    }
}

// ---------------- launch --------------------------------------------------------
extern "C" void kernel_launch(void* const* d_in, const int* in_sizes, int n_in,
                              void* d_out, int out_size)
{
    const float* hidden = (const float*)d_in[0];
    const float* aux    = (const float*)d_in[1];
    const float* wq1 = (const float*)d_in[2];  const float* bq1 = (const float*)d_in[3];
    const float* wk1 = (const float*)d_in[4];  const float* bk1 = (const float*)d_in[5];
    const float* wv1 = (const float*)d_in[6];  const float* bv1 = (const float*)d_in[7];
    const float* wo1 = (const float*)d_in[8];  const float* bo1 = (const float*)d_in[9];
    const float* wq2 = (const float*)d_in[10]; const float* bq2 = (const float*)d_in[11];
    const float* wk2 = (const float*)d_in[12]; const float* bk2 = (const float*)d_in[13];
    const float* wv2 = (const float*)d_in[14]; const float* bv2 = (const float*)d_in[15];
    const float* wo2 = (const float*)d_in[16]; const float* bo2 = (const float*)d_in[17];
    const float* g_aux = (const float*)d_in[18]; const float* b_aux = (const float*)d_in[19];
    const float* g_h   = (const float*)d_in[20]; const float* b_h   = (const float*)d_in[21];

    cudaFuncSetAttribute(hgemm_t,
        cudaFuncAttributeMaxDynamicSharedMemorySize, HT_SMEM);
    cudaFuncSetAttribute(hgemm_nn,
        cudaFuncAttributeMaxDynamicSharedMemorySize, HN_SMEM);

    float* scratch = nullptr;
    cudaGetSymbolAddress((void**)&scratch, g_scratch);

    // fp32 region
    float* out2p    = scratch;                 // 33,554,432
    float* out1f    = scratch + 33554432;      // 1,048,576
    float* bias_kvq = scratch + 34603008;      // 2048  [bk1|bv1|bq2]
    float* bias_kv2 = scratch + 34605056;      // 1536  [bk2|bv2]
    // fp16 region
    __half* hb = (__half*)(scratch + 34606592);
    __half* h_h   = hb;                        // 33,554,432
    __half* a_h   = hb + 33554432;             // 1,048,576
    __half* wk1h  = hb + OFF_WK1;
    __half* wq1h  = hb + OFF_WQ1;
    __half* wo1h  = hb + OFF_WO1;
    __half* wk2h  = hb + OFF_WK2;
    __half* wo2h  = hb + OFF_WO2;
    __half* kvq2  = hb + 39321600;             // [32768, 2048]
    __half* k1h   = kvq2;                      // cols 0..511,  ld 2048
    __half* v1h   = kvq2 + 512;                // cols 512..1535
    __half* q2h   = kvq2 + 1536;               // cols 1536..2047
    __half* q1h   = hb + 106430464;            // [2048, 512]
    __half* kv2   = hb + 107479040;            // [2048, 1536]
    __half* k2h   = kv2;                       // cols 0..511, ld 1536
    __half* v2h   = kv2 + 512;                 // cols 512..1535
    __half* ao1h  = hb + 110624768;            // [2048, 1024]
    __half* ao2h  = hb + 112721920;            // [32768, 1024]
    __half* out1h = hb + 146276352;            // [2048, 512]
    __half* attn1h= hb + 147324928;            // 67,108,864
    __half* attn2h= hb + 214433792;            // 67,108,864

    float* out     = (float*)d_out;
    float* aux_out = out + (size_t)B_ * HW_ * HID_;
    float* attn2   = aux_out + (size_t)B_ * K_ * AUX_;
    float* attn1   = attn2 + (size_t)B_ * NH_ * HW_ * K_;

    // --- pre-pass: fp16 conversions + bias concatenation ---
    cvt_kernel<<<16384, 256>>>(hidden, h_h);                     // launch 1
    cvt_kernel<<<512,   256>>>(aux,    a_h);                     // launch 2
    cvt_weights<<<2304, 256>>>(wk1, wv1, wq2, wq1, wo1, wk2, wv2, wo2, hb); // launch 3
    cudaMemcpyAsync(bias_kvq,        bk1, 512  * 4, cudaMemcpyDeviceToDevice);
    cudaMemcpyAsync(bias_kvq + 512,  bv1, 1024 * 4, cudaMemcpyDeviceToDevice);
    cudaMemcpyAsync(bias_kvq + 1536, bq2, 512  * 4, cudaMemcpyDeviceToDevice);
    cudaMemcpyAsync(bias_kv2,        bk2, 512  * 4, cudaMemcpyDeviceToDevice);
    cudaMemcpyAsync(bias_kv2 + 512,  bv2, 1024 * 4, cudaMemcpyDeviceToDevice);

    // --- projections ---
    hgemm_t<<<dim3(4, 16), 256, HT_SMEM>>>(a_h, wq1h, bq1, nullptr, q1h,  // launch 4
        512, 512, 512, 512, 0, 0, 0, 0, 0, 0, 1, 1.f);
    // fused k1|v1|q2: M=32768, N=2048, K=1024
    hgemm_t<<<dim3(16, 256), 256, HT_SMEM>>>(h_h, wk1h, bias_kvq, nullptr, kvq2, // launch 5
        1024, 1024, 1024, 2048, 0, 0, 0, 0, 0, 0, 1, 1.f);

    // --- pack attention: scores (b,h): 256 x 4096, headdim 64 --- (launch 6: profiled)
    hgemm_t<<<dim3(32, 2, 64), 256, HT_SMEM>>>(q1h, k1h, nullptr, attn1, nullptr,
        64, 512, 2048, 4096,
        (long long)K_ * QK_, 64,
        (long long)HW_ * 2048, 64,
        (long long)NH_ * K_ * HW_, (long long)K_ * HW_, NH_, SCALE_);
    softmax4096_kernel<<<16384, 256>>>(attn1, attn1h);
    hgemm_nn<<<dim3(1, 2, 64), 256, HN_SMEM>>>(attn1h, v1h, nullptr, ao1h,
        4096, 4096, 2048, 1024,
        (long long)NH_ * K_ * HW_, (long long)K_ * HW_,
        (long long)HW_ * 2048, HD_,
        (long long)K_ * HID_, HD_, NH_);
    hgemm_t<<<dim3(4, 16), 256, HT_SMEM>>>(ao1h, wo1h, bo1, out1f, out1h,
        1024, 1024, 1024, 512, 0, 0, 0, 0, 0, 0, 1, 1.f);
    add_ln_kernel<2><<<2048, 256>>>(aux, out1f, g_aux, b_aux, aux_out, 512);

    // --- unpack attention ---
    // fused k2|v2: M=2048, N=1536, K=512
    hgemm_t<<<dim3(12, 16), 256, HT_SMEM>>>(out1h, wk2h, bias_kv2, nullptr, kv2,
        512, 512, 512, 1536, 0, 0, 0, 0, 0, 0, 1, 1.f);
    hgemm_t<<<dim3(2, 32, 64), 256, HT_SMEM>>>(q2h, k2h, nullptr, attn2, nullptr,
        64, 2048, 1536, 256,
        (long long)HW_ * 2048, 64,
        (long long)K_ * 1536, 64,
        (long long)NH_ * HW_ * K_, (long long)HW_ * K_, NH_, SCALE_);
    softmax256_kernel<<<32768, 256>>>(attn2, attn2h);
    hgemm_nn<<<dim3(1, 32, 64), 256, HN_SMEM>>>(attn2h, v2h, nullptr, ao2h,
        256, 256, 1536, 1024,
        (long long)NH_ * HW_ * K_, (long long)HW_ * K_,
        (long long)K_ * 1536, HD_,
        (long long)HW_ * HID_, HD_, NH_);
    hgemm_t<<<dim3(8, 256), 256, HT_SMEM>>>(ao2h, wo2h, bo2, out2p, nullptr,
        1024, 1024, 1024, 1024, 0, 0, 0, 0, 0, 0, 1, 1.f);
    add_ln_kernel<4><<<32768, 256>>>(hidden, out2p, g_h, b_h, out, 1024);
}

// round 11
// speedup vs baseline: 1.9384x; 1.0000x over previous
#include <cuda_runtime.h>
#include <cuda_fp16.h>
#include <math.h>
#include <stdint.h>

#define B_    8
#define HW_   4096
#define K_    256
#define HID_  1024
#define AUX_  512
#define QK_   512
#define NH_   8
#define HD_   128
#define SCALE_ 0.08838834764831845f   // 1/sqrt(128)

// scratch: fp32 region (partials/out2p, out1f, bias concats) then fp16 region
__device__ float g_scratch[175377920];

// ---------------- helpers -----------------------------------------------------
__device__ __forceinline__ void cp16(void* s, const void* g) {
    uint32_t sa = (uint32_t)__cvta_generic_to_shared(s);
    asm volatile("cp.async.cg.shared.global [%0], [%1], 16;" :: "r"(sa), "l"(g));
}
__device__ __forceinline__ void ldsm4(uint32_t* r, uint32_t a) {
    asm volatile("ldmatrix.sync.aligned.m8n8.x4.shared.b16 {%0,%1,%2,%3}, [%4];"
        : "=r"(r[0]), "=r"(r[1]), "=r"(r[2]), "=r"(r[3]) : "r"(a));
}
__device__ __forceinline__ void ldsm4t(uint32_t* r, uint32_t a) {
    asm volatile("ldmatrix.sync.aligned.m8n8.x4.trans.shared.b16 {%0,%1,%2,%3}, [%4];"
        : "=r"(r[0]), "=r"(r[1]), "=r"(r[2]), "=r"(r[3]) : "r"(a));
}
__device__ __forceinline__ void mma16(float* c, const uint32_t* a, const uint32_t* b) {
    asm volatile(
        "mma.sync.aligned.m16n8k16.row.col.f32.f16.f16.f32 "
        "{%0,%1,%2,%3}, {%4,%5,%6,%7}, {%8,%9}, {%0,%1,%2,%3};"
        : "+f"(c[0]), "+f"(c[1]), "+f"(c[2]), "+f"(c[3])
        : "r"(a[0]), "r"(a[1]), "r"(a[2]), "r"(a[3]), "r"(b[0]), "r"(b[1]));
}
__device__ __forceinline__ void cvt8(const float* s, __half* d) {
    float4 a = *reinterpret_cast<const float4*>(s);
    float4 b = *reinterpret_cast<const float4*>(s + 4);
    __half2 h0 = __floats2half2_rn(a.x, a.y);
    __half2 h1 = __floats2half2_rn(a.z, a.w);
    __half2 h2 = __floats2half2_rn(b.x, b.y);
    __half2 h3 = __floats2half2_rn(b.z, b.w);
    uint4 o;
    o.x = *reinterpret_cast<uint32_t*>(&h0);
    o.y = *reinterpret_cast<uint32_t*>(&h1);
    o.z = *reinterpret_cast<uint32_t*>(&h2);
    o.w = *reinterpret_cast<uint32_t*>(&h3);
    *reinterpret_cast<uint4*>(d) = o;
}

// ---------------- fp32 -> fp16 conversion -------------------------------------
__global__ __launch_bounds__(256) void cvt_kernel(const float* __restrict__ x,
                                                  __half* __restrict__ y)
{
    const size_t i = ((size_t)blockIdx.x * 256 + threadIdx.x) * 8;
    cvt8(x + i, y + i);
}

// fp16-region half offsets (from hb)
#define OFF_WK1   34603008LL
#define OFF_WV1   35127296LL
#define OFF_WQ2   36175872LL
#define OFF_WQ1   36700160LL
#define OFF_WO1   36962304LL
#define OFF_WK2   37486592LL
#define OFF_WV2   37748736LL
#define OFF_WO2   38273024LL

__global__ __launch_bounds__(256) void cvt_weights(
    const float* __restrict__ wk1, const float* __restrict__ wv1,
    const float* __restrict__ wq2, const float* __restrict__ wq1,
    const float* __restrict__ wo1, const float* __restrict__ wk2,
    const float* __restrict__ wv2, const float* __restrict__ wo2,
    __half* __restrict__ hb)
{
    const int g = blockIdx.x * 256 + threadIdx.x;
    const float* s; long long d;
    if      (g < 65536)  { s = wk1 + (size_t)g * 8;            d = OFF_WK1 + (long long)g * 8; }
    else if (g < 196608) { s = wv1 + (size_t)(g - 65536)  * 8; d = OFF_WV1 + (long long)(g - 65536)  * 8; }
    else if (g < 262144) { s = wq2 + (size_t)(g - 196608) * 8; d = OFF_WQ2 + (long long)(g - 196608) * 8; }
    else if (g < 294912) { s = wq1 + (size_t)(g - 262144) * 8; d = OFF_WQ1 + (long long)(g - 262144) * 8; }
    else if (g < 360448) { s = wo1 + (size_t)(g - 294912) * 8; d = OFF_WO1 + (long long)(g - 294912) * 8; }
    else if (g < 393216) { s = wk2 + (size_t)(g - 360448) * 8; d = OFF_WK2 + (long long)(g - 360448) * 8; }
    else if (g < 458752) { s = wv2 + (size_t)(g - 393216) * 8; d = OFF_WV2 + (long long)(g - 393216) * 8; }
    else                 { s = wo2 + (size_t)(g - 458752) * 8; d = OFF_WO2 + (long long)(g - 458752) * 8; }
    cvt8(s, hb + d);
}

// ======== fp16 TRANSB GEMM ====================================================
#define HT_SA   72
#define HT_STG  (128 * HT_SA)
#define HT_PAIR (2 * HT_STG)
#define HT_SMEM (2 * HT_PAIR * 2)

__global__ __launch_bounds__(256, 2) void hgemm_t(
    const __half* __restrict__ A, const __half* __restrict__ Bm,
    const float* __restrict__ bias, float* __restrict__ Cf, __half* __restrict__ Ch,
    int Kd, int lda, int ldb, int ldc,
    long long sAb, long long sAh, long long sBb, long long sBh,
    long long sCb, long long sCh, int nh, float alpha)
{
    extern __shared__ __half hsm[];
    const int z = blockIdx.z, bb = z / nh, hh = z - bb * nh;
    A  += bb * sAb + hh * sAh;
    Bm += bb * sBb + hh * sBh;
    const long long cO = bb * sCb + hh * sCh;

    const int m0 = blockIdx.y * 128, n0 = blockIdx.x * 128;
    const int t = threadIdx.x, lane = t & 31, warp = t >> 5;
    const int wm = (warp >> 2) * 64, wn = (warp & 3) * 32;
    const uint32_t smb = (uint32_t)__cvta_generic_to_shared(hsm);

    float acc[4][4][4];
#pragma unroll
    for (int i = 0; i < 4; i++)
#pragma unroll
        for (int j = 0; j < 4; j++)
#pragma unroll
            for (int r = 0; r < 4; r++) acc[i][j][r] = 0.f;

    auto fill = [&](int s, int ck) {
        __half* Sa = hsm + s * HT_PAIR;
        __half* Sb = Sa + HT_STG;
        const int k0 = ck * 64;
#pragma unroll
        for (int i = 0; i < 4; i++) {
            int c = t + i * 256, row = c >> 3, o = (c & 7) * 8;
            cp16(&Sa[row * HT_SA + o], A + (size_t)(m0 + row) * lda + k0 + o);
        }
#pragma unroll
        for (int i = 0; i < 4; i++) {
            int c = t + i * 256, row = c >> 3, o = (c & 7) * 8;
            cp16(&Sb[row * HT_SA + o], Bm + (size_t)(n0 + row) * ldb + k0 + o);
        }
    };

    const int nchunk = Kd >> 6;
    fill(0, 0);
    asm volatile("cp.async.commit_group;");
    if (nchunk > 1) fill(1, 1);
    asm volatile("cp.async.commit_group;");

    const int lrow = lane & 15;
    const int lcol = (lane >> 4) * 8;

    for (int ck = 0; ck < nchunk; ck++) {
        if (ck + 1 >= nchunk) asm volatile("cp.async.wait_group 0;");
        else                  asm volatile("cp.async.wait_group 1;");
        __syncthreads();

        const uint32_t sA = smb + (uint32_t)((ck & 1) * HT_PAIR) * 2;
        const uint32_t sB = sA + HT_STG * 2;
#pragma unroll
        for (int ks = 0; ks < 4; ks++) {
            uint32_t af[4][4], bq[2][4];
#pragma unroll
            for (int mt = 0; mt < 4; mt++)
                ldsm4(af[mt], sA + 2 * ((wm + mt * 16 + lrow) * HT_SA + ks * 16 + lcol));
#pragma unroll
            for (int p = 0; p < 2; p++)
                ldsm4(bq[p], sB + 2 * ((wn + p * 16 + lrow) * HT_SA + ks * 16 + lcol));
#pragma unroll
            for (int mt = 0; mt < 4; mt++)
#pragma unroll
                for (int p = 0; p < 2; p++) {
                    uint32_t b0[2] = { bq[p][0], bq[p][2] };
                    uint32_t b1[2] = { bq[p][1], bq[p][3] };
                    mma16(acc[mt][2 * p],     af[mt], b0);
                    mma16(acc[mt][2 * p + 1], af[mt], b1);
                }
        }
        __syncthreads();
        if (ck + 2 < nchunk) fill(ck & 1, ck + 2);
        asm volatile("cp.async.commit_group;");
    }

    const int gid = lane >> 2, tig = lane & 3;
#pragma unroll
    for (int mt = 0; mt < 4; mt++) {
        const int row = m0 + wm + mt * 16 + gid;
#pragma unroll
        for (int nt = 0; nt < 4; nt++) {
            const int col = n0 + wn + nt * 8 + tig * 2;
            float b0v = 0.f, b1v = 0.f;
            if (bias) { b0v = bias[col]; b1v = bias[col + 1]; }
#pragma unroll
            for (int h = 0; h < 2; h++) {
                float2 v;
                v.x = acc[mt][nt][h * 2 + 0] * alpha + b0v;
                v.y = acc[mt][nt][h * 2 + 1] * alpha + b1v;
                const long long idx = cO + (long long)(row + h * 8) * ldc + col;
                if (Cf) *reinterpret_cast<float2*>(Cf + idx) = v;
                if (Ch) {
                    __half2 hv = __floats2half2_rn(v.x, v.y);
                    *reinterpret_cast<__half2*>(Ch + idx) = hv;
                }
            }
        }
    }
}

// ======== fp16 NN GEMM (attn @ V), optional split-K ===========================
// splitK==0: normal (blockIdx.x = N tile).  splitK!=0: blockIdx.x = K-slice
// index; Kd = slice length; partials (fp32) to Cf + blockIdx.x * pStride; n0=0.
#define HN_SB   136
#define HN_BSTG (64 * HN_SB)
#define HN_PAIR (HT_STG + HN_BSTG)
#define HN_SMEM (2 * HN_PAIR * 2)

__global__ __launch_bounds__(256, 2) void hgemm_nn(
    const __half* __restrict__ A, const __half* __restrict__ Bm,
    float* __restrict__ Cf, __half* __restrict__ Ch,
    int Kd, int lda, int ldb, int ldc,
    long long sAb, long long sAh, long long sBb, long long sBh,
    long long sCb, long long sCh, int nh, int splitK, long long pStride)
{
    extern __shared__ __half hsm[];
    const int z = blockIdx.z, bb = z / nh, hh = z - bb * nh;
    A  += bb * sAb + hh * sAh;
    Bm += bb * sBb + hh * sBh;
    long long cO = bb * sCb + hh * sCh;

    const int m0 = blockIdx.y * 128;
    const int n0 = splitK ? 0 : blockIdx.x * 128;
    const int kOff = splitK ? blockIdx.x * Kd : 0;
    if (splitK) cO += (long long)blockIdx.x * pStride;

    const int t = threadIdx.x, lane = t & 31, warp = t >> 5;
    const int wm = (warp >> 2) * 64, wn = (warp & 3) * 32;
    const uint32_t smb = (uint32_t)__cvta_generic_to_shared(hsm);

    float acc[4][4][4];
#pragma unroll
    for (int i = 0; i < 4; i++)
#pragma unroll
        for (int j = 0; j < 4; j++)
#pragma unroll
            for (int r = 0; r < 4; r++) acc[i][j][r] = 0.f;

    auto fill = [&](int s, int ck) {
        __half* Sa = hsm + s * HN_PAIR;
        __half* Sb = Sa + HT_STG;
        const int k0 = kOff + ck * 64;
#pragma unroll
        for (int i = 0; i < 4; i++) {
            int c = t + i * 256, row = c >> 3, o = (c & 7) * 8;
            cp16(&Sa[row * HT_SA + o], A + (size_t)(m0 + row) * lda + k0 + o);
        }
#pragma unroll
        for (int i = 0; i < 4; i++) {
            int c = t + i * 256, row = c >> 4, o = (c & 15) * 8;
            cp16(&Sb[row * HN_SB + o], Bm + (size_t)(k0 + row) * ldb + n0 + o);
        }
    };

    const int nchunk = Kd >> 6;
    fill(0, 0);
    asm volatile("cp.async.commit_group;");
    if (nchunk > 1) fill(1, 1);
    asm volatile("cp.async.commit_group;");

    const int lrow  = lane & 15;
    const int lcol  = (lane >> 4) * 8;
    const int tkrow = ((lane >> 3) & 1) * 8 + (lane & 7);
    const int tncol = (lane >> 4) * 8;

    for (int ck = 0; ck < nchunk; ck++) {
        if (ck + 1 >= nchunk) asm volatile("cp.async.wait_group 0;");
        else                  asm volatile("cp.async.wait_group 1;");
        __syncthreads();

        const uint32_t sA = smb + (uint32_t)((ck & 1) * HN_PAIR) * 2;
        const uint32_t sB = sA + HT_STG * 2;
#pragma unroll
        for (int ks = 0; ks < 4; ks++) {
            uint32_t af[4][4], bq[2][4];
#pragma unroll
            for (int mt = 0; mt < 4; mt++)
                ldsm4(af[mt], sA + 2 * ((wm + mt * 16 + lrow) * HT_SA + ks * 16 + lcol));
#pragma unroll
            for (int p = 0; p < 2; p++)
                ldsm4t(bq[p], sB + 2 * ((ks * 16 + tkrow) * HN_SB + wn + p * 16 + tncol));
#pragma unroll
            for (int mt = 0; mt < 4; mt++)
#pragma unroll
                for (int p = 0; p < 2; p++) {
                    uint32_t b0[2] = { bq[p][0], bq[p][1] };
                    uint32_t b1[2] = { bq[p][2], bq[p][3] };
                    mma16(acc[mt][2 * p],     af[mt], b0);
                    mma16(acc[mt][2 * p + 1], af[mt], b1);
                }
        }
        __syncthreads();
        if (ck + 2 < nchunk) fill(ck & 1, ck + 2);
        asm volatile("cp.async.commit_group;");
    }

    const int gid = lane >> 2, tig = lane & 3;
#pragma unroll
    for (int mt = 0; mt < 4; mt++) {
        const int row = m0 + wm + mt * 16 + gid;
#pragma unroll
        for (int nt = 0; nt < 4; nt++) {
            const int col = n0 + wn + nt * 8 + tig * 2;
#pragma unroll
            for (int h = 0; h < 2; h++) {
                float2 v;
                v.x = acc[mt][nt][h * 2 + 0];
                v.y = acc[mt][nt][h * 2 + 1];
                const long long idx = cO + (long long)(row + h * 8) * ldc + col;
                if (Cf) *reinterpret_cast<float2*>(Cf + idx) = v;
                if (Ch && !splitK) {
                    __half2 hv = __floats2half2_rn(v.x, v.y);
                    *reinterpret_cast<__half2*>(Ch + idx) = hv;
                }
            }
        }
    }
}

// ---------------- split-K reduction: sum 8 fp32 partials -> fp16 --------------
__global__ __launch_bounds__(256) void reduce8_kernel(
    const float* __restrict__ P, __half* __restrict__ out, long long pStride)
{
    const long long i = ((long long)blockIdx.x * 256 + threadIdx.x) * 4;
    float4 a = *reinterpret_cast<const float4*>(P + i);
#pragma unroll
    for (int s = 1; s < 8; s++) {
        float4 b = *reinterpret_cast<const float4*>(P + s * pStride + i);
        a.x += b.x; a.y += b.y; a.z += b.z; a.w += b.w;
    }
    __half2 h0 = __floats2half2_rn(a.x, a.y);
    __half2 h1 = __floats2half2_rn(a.z, a.w);
    uint2 o;
    o.x = *reinterpret_cast<uint32_t*>(&h0);
    o.y = *reinterpret_cast<uint32_t*>(&h1);
    *reinterpret_cast<uint2*>(out + i) = o;
}

// ---------------- softmax, L = 4096 -------------------------------------------
__global__ __launch_bounds__(256) void softmax4096_kernel(float* __restrict__ X,
                                                          __half* __restrict__ Xh)
{
    float* x = X + (size_t)blockIdx.x * 4096;
    __half* xh = Xh + (size_t)blockIdx.x * 4096;
    const int t = threadIdx.x;
    float v[16];
    float m = -1e30f;
#pragma unroll
    for (int i = 0; i < 16; i++) { v[i] = x[t + i * 256]; m = fmaxf(m, v[i]); }
    __shared__ float red[8];
    const int lane = t & 31, w = t >> 5;
#pragma unroll
    for (int o = 16; o > 0; o >>= 1) m = fmaxf(m, __shfl_xor_sync(0xffffffffu, m, o));
    if (lane == 0) red[w] = m;
    __syncthreads();
    float bm = red[0];
#pragma unroll
    for (int i = 1; i < 8; i++) bm = fmaxf(bm, red[i]);
    float s = 0.f;
#pragma unroll
    for (int i = 0; i < 16; i++) { v[i] = __expf(v[i] - bm); s += v[i]; }
#pragma unroll
    for (int o = 16; o > 0; o >>= 1) s += __shfl_xor_sync(0xffffffffu, s, o);
    __syncthreads();
    if (lane == 0) red[w] = s;
    __syncthreads();
    float bs = 0.f;
#pragma unroll
    for (int i = 0; i < 8; i++) bs += red[i];
    const float inv = 1.0f / bs;
#pragma unroll
    for (int i = 0; i < 16; i++) {
        float r = v[i] * inv;
        x[t + i * 256]  = r;
        xh[t + i * 256] = __float2half_rn(r);
    }
}

// ---------------- softmax, L = 256 --------------------------------------------
__global__ __launch_bounds__(256) void softmax256_kernel(float* __restrict__ X,
                                                         __half* __restrict__ Xh)
{
    const int lane = threadIdx.x & 31;
    const int w    = threadIdx.x >> 5;
    const size_t rb = ((size_t)blockIdx.x * 8 + w) * 256;
    float* x = X + rb;
    __half* xh = Xh + rb;
    float v[8];
    float m = -1e30f;
#pragma unroll
    for (int i = 0; i < 8; i++) { v[i] = x[lane + i * 32]; m = fmaxf(m, v[i]); }
#pragma unroll
    for (int o = 16; o > 0; o >>= 1) m = fmaxf(m, __shfl_xor_sync(0xffffffffu, m, o));
    float s = 0.f;
#pragma unroll
    for (int i = 0; i < 8; i++) { v[i] = __expf(v[i] - m); s += v[i]; }
#pragma unroll
    for (int o = 16; o > 0; o >>= 1) s += __shfl_xor_sync(0xffffffffu, s, o);
    const float inv = 1.0f / s;
#pragma unroll
    for (int i = 0; i < 8; i++) {
        float r = v[i] * inv;
        x[lane + i * 32]  = r;
        xh[lane + i * 32] = __float2half_rn(r);
    }
}

// ---------------- residual add + LayerNorm ------------------------------------
template<int VPT>
__global__ __launch_bounds__(256) void add_ln_kernel(
    const float* __restrict__ R, const float* __restrict__ X,
    const float* __restrict__ g, const float* __restrict__ bta,
    float* __restrict__ Y, int D)
{
    const size_t row = blockIdx.x;
    const float* r = R + row * D;
    const float* x = X + row * D;
    float* y = Y + row * D;
    const int t = threadIdx.x;
    float v[VPT];
    float s = 0.f, sq = 0.f;
#pragma unroll
    for (int i = 0; i < VPT; i++) {
        const int c = t + i * 256;
        v[i] = r[c] + x[c];
        s += v[i]; sq += v[i] * v[i];
    }
    const int lane = t & 31, w = t >> 5;
#pragma unroll
    for (int o = 16; o > 0; o >>= 1) {
        s  += __shfl_xor_sync(0xffffffffu, s, o);
        sq += __shfl_xor_sync(0xffffffffu, sq, o);
    }
    __shared__ float rs[8], rq[8];
    if (lane == 0) { rs[w] = s; rq[w] = sq; }
    __syncthreads();
    s = 0.f; sq = 0.f;
#pragma unroll
    for (int i = 0; i < 8; i++) { s += rs[i]; sq += rq[i]; }
    const float mean = s / D;
    const float var  = sq / D - mean * mean;
    const float inv  = rsqrtf(var + 1e-5f);
#pragma unroll
    for (int i = 0; i < VPT; i++) {
        const int c = t + i * 256;
        y[c] = (v[i] - mean) * inv * g[c] + bta[c];
    }
}

// ---------------- launch --------------------------------------------------------
extern "C" void kernel_launch(void* const* d_in, const int* in_sizes, int n_in,
                              void* d_out, int out_size)
{
    const float* hidden = (const float*)d_in[0];
    const float* aux    = (const float*)d_in[1];
    const float* wq1 = (const float*)d_in[2];  const float* bq1 = (const float*)d_in[3];
    const float* wk1 = (const float*)d_in[4];  const float* bk1 = (const float*)d_in[5];
    const float* wv1 = (const float*)d_in[6];  const float* bv1 = (const float*)d_in[7];
    const float* wo1 = (const float*)d_in[8];  const float* bo1 = (const float*)d_in[9];
    const float* wq2 = (const float*)d_in[10]; const float* bq2 = (const float*)d_in[11];
    const float* wk2 = (const float*)d_in[12]; const float* bk2 = (const float*)d_in[13];
    const float* wv2 = (const float*)d_in[14]; const float* bv2 = (const float*)d_in[15];
    const float* wo2 = (const float*)d_in[16]; const float* bo2 = (const float*)d_in[17];
    const float* g_aux = (const float*)d_in[18]; const float* b_aux = (const float*)d_in[19];
    const float* g_h   = (const float*)d_in[20]; const float* b_h   = (const float*)d_in[21];

    cudaFuncSetAttribute(hgemm_t,
        cudaFuncAttributeMaxDynamicSharedMemorySize, HT_SMEM);
    cudaFuncSetAttribute(hgemm_nn,
        cudaFuncAttributeMaxDynamicSharedMemorySize, HN_SMEM);

    float* scratch = nullptr;
    cudaGetSymbolAddress((void**)&scratch, g_scratch);

    // fp32 region: partials (16.8M) alias out2p (33.5M) — disjoint liveness
    float* partials = scratch;                 // 8 x 2,097,152
    float* out2p    = scratch;                 // 33,554,432 (used after reduction)
    float* out1f    = scratch + 33554432;      // 1,048,576
    float* bias_kvq = scratch + 34603008;      // 2048
    float* bias_kv2 = scratch + 34605056;      // 1536
    // fp16 region
    __half* hb = (__half*)(scratch + 34606592);
    __half* h_h   = hb;
    __half* a_h   = hb + 33554432;
    __half* wk1h  = hb + OFF_WK1;
    __half* wq1h  = hb + OFF_WQ1;
    __half* wo1h  = hb + OFF_WO1;
    __half* wk2h  = hb + OFF_WK2;
    __half* wo2h  = hb + OFF_WO2;
    __half* kvq2  = hb + 39321600;             // [32768, 2048]
    __half* k1h   = kvq2;
    __half* v1h   = kvq2 + 512;
    __half* q2h   = kvq2 + 1536;
    __half* q1h   = hb + 106430464;
    __half* kv2   = hb + 107479040;            // [2048, 1536]
    __half* k2h   = kv2;
    __half* v2h   = kv2 + 512;
    __half* ao1h  = hb + 110624768;            // [2048, 1024]
    __half* ao2h  = hb + 112721920;            // [32768, 1024]
    __half* out1h = hb + 146276352;
    __half* attn1h= hb + 147324928;
    __half* attn2h= hb + 214433792;

    float* out     = (float*)d_out;
    float* aux_out = out + (size_t)B_ * HW_ * HID_;
    float* attn2   = aux_out + (size_t)B_ * K_ * AUX_;
    float* attn1   = attn2 + (size_t)B_ * NH_ * HW_ * K_;

    // --- bias concats first (memcpys), then conversions ---
    cudaMemcpyAsync(bias_kvq,        bk1, 512  * 4, cudaMemcpyDeviceToDevice);
    cudaMemcpyAsync(bias_kvq + 512,  bv1, 1024 * 4, cudaMemcpyDeviceToDevice);
    cudaMemcpyAsync(bias_kvq + 1536, bq2, 512  * 4, cudaMemcpyDeviceToDevice);
    cudaMemcpyAsync(bias_kv2,        bk2, 512  * 4, cudaMemcpyDeviceToDevice);
    cudaMemcpyAsync(bias_kv2 + 512,  bv2, 1024 * 4, cudaMemcpyDeviceToDevice);
    cvt_kernel<<<16384, 256>>>(hidden, h_h);
    cvt_kernel<<<512,   256>>>(aux,    a_h);
    cvt_weights<<<2304, 256>>>(wk1, wv1, wq2, wq1, wo1, wk2, wv2, wo2, hb);

    // --- projections (fused kvq2 first so it lands in the profile window) ---
    hgemm_t<<<dim3(16, 256), 256, HT_SMEM>>>(h_h, wk1h, bias_kvq, nullptr, kvq2,
        1024, 1024, 1024, 2048, 0, 0, 0, 0, 0, 0, 1, 1.f);
    hgemm_t<<<dim3(4, 16), 256, HT_SMEM>>>(a_h, wq1h, bq1, nullptr, q1h,
        512, 512, 512, 512, 0, 0, 0, 0, 0, 0, 1, 1.f);

    // --- pack attention ---
    hgemm_t<<<dim3(32, 2, 64), 256, HT_SMEM>>>(q1h, k1h, nullptr, attn1, nullptr,
        64, 512, 2048, 4096,
        (long long)K_ * QK_, 64,
        (long long)HW_ * 2048, 64,
        (long long)NH_ * K_ * HW_, (long long)K_ * HW_, NH_, SCALE_);
    softmax4096_kernel<<<16384, 256>>>(attn1, attn1h);
    // attn1 @ v1 with split-K=8: K=4096 -> 8 x 512, partials fp32
    hgemm_nn<<<dim3(8, 2, 64), 256, HN_SMEM>>>(attn1h, v1h, partials, nullptr,
        512, 4096, 2048, 1024,
        (long long)NH_ * K_ * HW_, (long long)K_ * HW_,
        (long long)HW_ * 2048, HD_,
        (long long)K_ * HID_, HD_, NH_, 1, 2097152LL);
    reduce8_kernel<<<2048, 256>>>(partials, ao1h, 2097152LL);
    hgemm_t<<<dim3(4, 16), 256, HT_SMEM>>>(ao1h, wo1h, bo1, out1f, out1h,
        1024, 1024, 1024, 512, 0, 0, 0, 0, 0, 0, 1, 1.f);
    add_ln_kernel<2><<<2048, 256>>>(aux, out1f, g_aux, b_aux, aux_out, 512);

    // --- unpack attention ---
    hgemm_t<<<dim3(12, 16), 256, HT_SMEM>>>(out1h, wk2h, bias_kv2, nullptr, kv2,
        512, 512, 512, 1536, 0, 0, 0, 0, 0, 0, 1, 1.f);
    hgemm_t<<<dim3(2, 32, 64), 256, HT_SMEM>>>(q2h, k2h, nullptr, attn2, nullptr,
        64, 2048, 1536, 256,
        (long long)HW_ * 2048, 64,
        (long long)K_ * 1536, 64,
        (long long)NH_ * HW_ * K_, (long long)HW_ * K_, NH_, SCALE_);
    softmax256_kernel<<<32768, 256>>>(attn2, attn2h);
    hgemm_nn<<<dim3(1, 32, 64), 256, HN_SMEM>>>(attn2h, v2h, nullptr, ao2h,
        256, 256, 1536, 1024,
        (long long)NH_ * HW_ * K_, (long long)HW_ * K_,
        (long long)K_ * 1536, HD_,
        (long long)HW_ * HID_, HD_, NH_, 0, 0);
    hgemm_t<<<dim3(8, 256), 256, HT_SMEM>>>(ao2h, wo2h, bo2, out2p, nullptr,
        1024, 1024, 1024, 1024, 0, 0, 0, 0, 0, 0, 1, 1.f);
    add_ln_kernel<4><<<32768, 256>>>(hidden, out2p, g_h, b_h, out, 1024);
}